// round 14
// baseline (speedup 1.0000x reference)
#include <cuda_runtime.h>
#include <cuda_bf16.h>
#include <cuda_fp16.h>
#include <math.h>
#include <stdint.h>

// Problem constants
#define NUM_HEADS 16
#define HIDDEN 2048
#define HEAD_SIZE 128
#define ROTARY_DIM 32
#define ROTARY_HALF 16
#define BATCH 4
#define SEQ 1024
#define TOTAL (BATCH * SEQ)
#define QKV_N (3 * HIDDEN)
#define QKV_ROW 6144
#define HEAD_STRIDE 384

#define NEG_INF (-1e30f)

// Scratch
__device__ float g_qkv[(size_t)TOTAL * QKV_N];
__device__ __half g_hid_h[(size_t)TOTAL * HIDDEN];
__device__ __half g_wqkv_h[(size_t)QKV_N * HIDDEN];
__device__ __half g_wd_h[(size_t)HIDDEN * HIDDEN];
__device__ __half g_attn_h[(size_t)TOTAL * HIDDEN];
// Precomputed split attention operands (bf16)
__device__ __nv_bfloat16 g_qh[(size_t)TOTAL * HIDDEN];
__device__ __nv_bfloat16 g_ql[(size_t)TOTAL * HIDDEN];
__device__ __nv_bfloat16 g_kh[(size_t)TOTAL * HIDDEN];
__device__ __nv_bfloat16 g_kl[(size_t)TOTAL * HIDDEN];
// V transposed split: [h*128+d][b*1024+j]
__device__ __nv_bfloat16 g_vth[(size_t)NUM_HEADS * HEAD_SIZE * TOTAL];
__device__ __nv_bfloat16 g_vtl[(size_t)NUM_HEADS * HEAD_SIZE * TOTAL];

// ---------------------------------------------------------------------------
__device__ __forceinline__ void mma_bf16(float* d, const unsigned* a, const unsigned* b) {
    asm volatile(
        "mma.sync.aligned.m16n8k16.row.col.f32.bf16.bf16.f32 "
        "{%0,%1,%2,%3}, {%4,%5,%6,%7}, {%8,%9}, {%0,%1,%2,%3};"
        : "+f"(d[0]), "+f"(d[1]), "+f"(d[2]), "+f"(d[3])
        : "r"(a[0]), "r"(a[1]), "r"(a[2]), "r"(a[3]), "r"(b[0]), "r"(b[1]));
}
__device__ __forceinline__ void mma_f16(float* d, const unsigned* a, const unsigned* b) {
    asm volatile(
        "mma.sync.aligned.m16n8k16.row.col.f32.f16.f16.f32 "
        "{%0,%1,%2,%3}, {%4,%5,%6,%7}, {%8,%9}, {%0,%1,%2,%3};"
        : "+f"(d[0]), "+f"(d[1]), "+f"(d[2]), "+f"(d[3])
        : "r"(a[0]), "r"(a[1]), "r"(a[2]), "r"(a[3]), "r"(b[0]), "r"(b[1]));
}

__device__ __forceinline__ void ldsm_x4(unsigned* r, unsigned saddr) {
    asm volatile("ldmatrix.sync.aligned.m8n8.x4.shared.b16 {%0,%1,%2,%3}, [%4];"
        : "=r"(r[0]), "=r"(r[1]), "=r"(r[2]), "=r"(r[3]) : "r"(saddr));
}

__device__ __forceinline__ unsigned pack_bf2(float lo, float hi) {
    __nv_bfloat162 t = __floats2bfloat162_rn(lo, hi);
    return *reinterpret_cast<unsigned*>(&t);
}
__device__ __forceinline__ unsigned pack_hf2(float lo, float hi) {
    __half2 t = __floats2half2_rn(lo, hi);
    return *reinterpret_cast<unsigned*>(&t);
}

__device__ __forceinline__ void cp16h(__half* smem_dst, const __half* gsrc) {
    unsigned saddr = (unsigned)__cvta_generic_to_shared(smem_dst);
    asm volatile("cp.async.cg.shared.global [%0], [%1], 16;" :: "r"(saddr), "l"(gsrc));
}
#define CP_COMMIT() asm volatile("cp.async.commit_group;" ::: "memory")
#define CP_WAIT1()  asm volatile("cp.async.wait_group 1;" ::: "memory")

// ---------------------------------------------------------------------------
// Single-product fp16 NT GEMM on HMMA: C = fp16(A) * fp16(B) + bias, fp32 acc.
// CTA 128x128, 8 warps (4m x 2n), BK=64, 3-stage cp.async ring, ldmatrix,
// 2 CTAs/SM. K-accumulation order identical to the BK=32 version.
// ---------------------------------------------------------------------------
#define PS 72                               // padded row stride (half elems) for BK=64
#define MAT_ELEMS (128 * PS)                // 9216
#define STAGE_ELEMS (2 * MAT_ELEMS)
#define NSTAGES 3
#define GEMM_SMEM_BYTES (NSTAGES * STAGE_ELEMS * 2)   // 110592 bytes

__global__ __launch_bounds__(256, 2)
void gemm_f16_nt_bias(const __half* __restrict__ A, const __half* __restrict__ B,
                      const float* __restrict__ bias, float* __restrict__ C,
                      int N, int K) {
    extern __shared__ __half smem[];
    const unsigned sbase = (unsigned)__cvta_generic_to_shared(smem);
    const int tid  = threadIdx.x;
    const int lane = tid & 31;
    const int wid  = tid >> 5;
    const int bm = blockIdx.y * 128;
    const int bn = blockIdx.x * 128;
    const int wm = (wid >> 1) * 32;
    const int wn = (wid & 1) * 64;

    float acc[2][8][4];
#pragma unroll
    for (int i = 0; i < 2; i++)
#pragma unroll
        for (int j = 0; j < 8; j++)
#pragma unroll
            for (int k = 0; k < 4; k++) acc[i][j][k] = 0.f;

    // per-chunk tile is 128 rows x 64 halfs per matrix; thread owns 32 halfs
    const int ldrow = tid >> 1;
    const int ldoff = (tid & 1) * 32;
    const __half* gA = A + (size_t)(bm + ldrow) * K + ldoff;
    const __half* gB = B + (size_t)(bn + ldrow) * K + ldoff;
    const int eo = ldrow * PS + ldoff;

    auto issue_load = [&](int c, int s) {
        const int off = c * 64;
        __half* st = smem + s * STAGE_ELEMS + eo;
        cp16h(st,                  gA + off);
        cp16h(st + 8,              gA + off + 8);
        cp16h(st + 16,             gA + off + 16);
        cp16h(st + 24,             gA + off + 24);
        cp16h(st + MAT_ELEMS,      gB + off);
        cp16h(st + MAT_ELEMS + 8,  gB + off + 8);
        cp16h(st + MAT_ELEMS + 16, gB + off + 16);
        cp16h(st + MAT_ELEMS + 24, gB + off + 24);
    };

    const int li = lane & 7;
    const int lm = lane >> 3;
    const int aoff0 = (wm + 0  + (lm & 1) * 8 + li) * PS + (lm >> 1) * 8;
    const int aoff1 = (wm + 16 + (lm & 1) * 8 + li) * PS + (lm >> 1) * 8;
    int boff[4];
#pragma unroll
    for (int p = 0; p < 4; p++)
        boff[p] = (wn + p * 16 + (lm >> 1) * 8 + li) * PS + (lm & 1) * 8;

    auto compute = [&](int s) {
        const unsigned stg = sbase + (s * STAGE_ELEMS) * 2;
        const unsigned sA = stg;
        const unsigned sB = stg + MAT_ELEMS * 2;
#pragma unroll
        for (int ks = 0; ks < 4; ks++) {
            const int kc2 = ks * 16 * 2;
            unsigned a[2][4];
            ldsm_x4(a[0], sA + aoff0 * 2 + kc2);
            ldsm_x4(a[1], sA + aoff1 * 2 + kc2);
            unsigned bh[4][4];
#pragma unroll
            for (int p = 0; p < 4; p++)
                ldsm_x4(bh[p], sB + boff[p] * 2 + kc2);
#pragma unroll
            for (int nf = 0; nf < 8; nf++) {
                const unsigned* bf = &bh[nf >> 1][(nf & 1) * 2];
                mma_f16(acc[0][nf], a[0], bf);
                mma_f16(acc[1][nf], a[1], bf);
            }
        }
    };

    const int nchunks = K / 64;
    issue_load(0, 0); CP_COMMIT();
    issue_load(1, 1); CP_COMMIT();

    int s = 0;
    for (int c = 0; c < nchunks; c++) {
        CP_WAIT1();
        __syncthreads();
        compute(s);
        // chunk c+2 -> stage (s+2)%3, which held chunk c-1 (drained by barrier)
        if (c + 2 < nchunks) issue_load(c + 2, (s + 2) % 3);
        CP_COMMIT();
        s = (s == 2) ? 0 : s + 1;
    }

    const int r = lane >> 2;
#pragma unroll
    for (int mf = 0; mf < 2; mf++) {
        const int row0 = bm + wm + mf * 16 + r;
#pragma unroll
        for (int nf = 0; nf < 8; nf++) {
            const int cn = bn + wn + nf * 8 + (lane & 3) * 2;
            float2 o0, o1;
            o0.x = acc[mf][nf][0] + bias[cn];
            o0.y = acc[mf][nf][1] + bias[cn + 1];
            o1.x = acc[mf][nf][2] + bias[cn];
            o1.y = acc[mf][nf][3] + bias[cn + 1];
            *(float2*)(C + (size_t)row0 * N + cn)       = o0;
            *(float2*)(C + (size_t)(row0 + 8) * N + cn) = o1;
        }
    }
}

// ---------------------------------------------------------------------------
// fp32 -> fp16 conversion, vectorized
// ---------------------------------------------------------------------------
__global__ __launch_bounds__(256)
void cvt_f16_v4(const float4* __restrict__ x, uint2* __restrict__ hi, int n4) {
    int i = blockIdx.x * 256 + threadIdx.x;
    if (i >= n4) return;
    float4 v = x[i];
    uint2 ho;
    ho.x = pack_hf2(v.x, v.y);
    ho.y = pack_hf2(v.z, v.w);
    hi[i] = ho;
}

// ---------------------------------------------------------------------------
// Fused rotary + bf16 hi/lo split of Q (scale folded) and K (validated R12).
// ---------------------------------------------------------------------------
__global__ __launch_bounds__(256)
void rotary_split_qk(const float* __restrict__ qkv,
                     __nv_bfloat16* __restrict__ qh, __nv_bfloat16* __restrict__ ql,
                     __nv_bfloat16* __restrict__ kh, __nv_bfloat16* __restrict__ kl) {
    const int t = blockIdx.x;
    const int n0 = threadIdx.x * 8;
    const int h = n0 >> 7;
    const int d0 = n0 & 127;
    const float scale = 0.088388347648318447f;
    const float pos = (float)(t % SEQ);

    const float* qb = qkv + (size_t)t * QKV_ROW + h * HEAD_STRIDE;
    float qv[8], kv[8];
#pragma unroll
    for (int i = 0; i < 8; i++) {
        const int d = d0 + i;
        float xq = qb[d], xk = qb[HEAD_SIZE + d];
        if (d < ROTARY_DIM) {
            const int j = (d < ROTARY_HALF) ? d : d - ROTARY_HALF;
            const float inv_freq = powf(10000.0f, -(2.0f * (float)j) / (float)ROTARY_DIM);
            const float f = pos * inv_freq;
            const float c = cosf(f);
            const float s = sinf(f);
            if (d < ROTARY_HALF) {
                float xq2 = qb[d + ROTARY_HALF], xk2 = qb[HEAD_SIZE + d + ROTARY_HALF];
                xq = xq * c - xq2 * s;
                xk = xk * c - xk2 * s;
            } else {
                float xq1 = qb[d - ROTARY_HALF], xk1 = qb[HEAD_SIZE + d - ROTARY_HALF];
                xq = xq1 * s + xq * c;
                xk = xk1 * s + xk * c;
            }
        }
        qv[i] = xq * scale;
        kv[i] = xk;
    }

    const size_t o = (size_t)t * HIDDEN + n0;
    unsigned rqh[4], rql[4], rkh[4], rkl[4];
#pragma unroll
    for (int i = 0; i < 4; i++) {
        float a = qv[2 * i], b2 = qv[2 * i + 1];
        float ha = __bfloat162float(__float2bfloat16(a));
        float hb = __bfloat162float(__float2bfloat16(b2));
        rqh[i] = pack_bf2(a, b2);
        rql[i] = pack_bf2(a - ha, b2 - hb);
        float ka = kv[2 * i], kb2 = kv[2 * i + 1];
        float hka = __bfloat162float(__float2bfloat16(ka));
        float hkb = __bfloat162float(__float2bfloat16(kb2));
        rkh[i] = pack_bf2(ka, kb2);
        rkl[i] = pack_bf2(ka - hka, kb2 - hkb);
    }
    *(uint4*)(qh + o) = *(uint4*)rqh;
    *(uint4*)(ql + o) = *(uint4*)rql;
    *(uint4*)(kh + o) = *(uint4*)rkh;
    *(uint4*)(kl + o) = *(uint4*)rkl;
}

// ---------------------------------------------------------------------------
// V split + transpose (validated R12).
// ---------------------------------------------------------------------------
__global__ __launch_bounds__(256)
void v_split_T(const float* __restrict__ qkv,
               __nv_bfloat16* __restrict__ vth, __nv_bfloat16* __restrict__ vtl) {
    __shared__ float s[64][65];
    const int tid = threadIdx.x;
    const int j0 = blockIdx.x * 64;
    const int d0 = blockIdx.y * 64;
    const int b  = blockIdx.z >> 4;
    const int h  = blockIdx.z & 15;

    {
        const int jr = tid >> 4;
        const int c4 = (tid & 15) * 4;
#pragma unroll
        for (int it = 0; it < 4; it++) {
            const int j = jr + it * 16;
            const float* src = qkv + (size_t)(b * SEQ + j0 + j) * QKV_ROW
                               + h * HEAD_STRIDE + 2 * HEAD_SIZE + d0 + c4;
            float4 v = *(const float4*)src;
            s[j][c4 + 0] = v.x; s[j][c4 + 1] = v.y;
            s[j][c4 + 2] = v.z; s[j][c4 + 3] = v.w;
        }
    }
    __syncthreads();

    {
        const int d = tid >> 2;
        const int part = tid & 3;
        unsigned rh[8], rl[8];
#pragma unroll
        for (int i = 0; i < 8; i++) {
            float a = s[part * 16 + 2 * i][d];
            float b2 = s[part * 16 + 2 * i + 1][d];
            float ha = __bfloat162float(__float2bfloat16(a));
            float hb = __bfloat162float(__float2bfloat16(b2));
            rh[i] = pack_bf2(a, b2);
            rl[i] = pack_bf2(a - ha, b2 - hb);
        }
        const size_t o = (size_t)(h * HEAD_SIZE + d0 + d) * TOTAL + b * SEQ + j0 + part * 16;
        *(uint4*)(vth + o)     = *(uint4*)rh;
        *(uint4*)(vth + o + 8) = *(uint4*)(rh + 4);
        *(uint4*)(vtl + o)     = *(uint4*)rl;
        *(uint4*)(vtl + o + 8) = *(uint4*)(rl + 4);
    }
}

// ---------------------------------------------------------------------------
// HMMA flash attention (bf16 3-product, validated). fp16 single epilogue.
// ---------------------------------------------------------------------------
#define QPS 136
#define KPS 136
#define VPS 72
#define FA_QT 128
#define FA_KT 64
#define FA_SMEM_BYTES ((2 * 128 * QPS + 2 * 64 * KPS + 2 * 128 * VPS) * 2)

__global__ __launch_bounds__(256)
void flash_attn_mma(const __nv_bfloat16* __restrict__ gqh, const __nv_bfloat16* __restrict__ gql,
                    const __nv_bfloat16* __restrict__ gkh, const __nv_bfloat16* __restrict__ gkl,
                    const __nv_bfloat16* __restrict__ gvth, const __nv_bfloat16* __restrict__ gvtl,
                    __half* __restrict__ out_h) {
    extern __shared__ __nv_bfloat16 sm[];
    __nv_bfloat16* Qh = sm;
    __nv_bfloat16* Ql = Qh + 128 * QPS;
    __nv_bfloat16* Kh = Ql + 128 * QPS;
    __nv_bfloat16* Kl = Kh + 64 * KPS;
    __nv_bfloat16* Vh = Kl + 64 * KPS;
    __nv_bfloat16* Vl = Vh + 128 * VPS;

    const int qt = blockIdx.x, h = blockIdx.y, b = blockIdx.z;
    const int tid = threadIdx.x, lane = tid & 31, wid = tid >> 5;
    const int r = lane >> 2, cg = lane & 3;
    const int qbase = qt * FA_QT;

    {
        const int row = tid >> 1;
        const int c0 = (tid & 1) * 64;
        const size_t so = (size_t)(b * SEQ + qbase + row) * HIDDEN + h * HEAD_SIZE + c0;
        const uint4* sh = (const uint4*)(gqh + so);
        const uint4* sl = (const uint4*)(gql + so);
        uint4* dh = (uint4*)(Qh + row * QPS + c0);
        uint4* dl = (uint4*)(Ql + row * QPS + c0);
#pragma unroll
        for (int i = 0; i < 8; i++) { dh[i] = sh[i]; dl[i] = sl[i]; }
    }

    const int qlo = qbase + wid * 16;
    const int q0 = qlo + r, q1 = q0 + 8;

    float O[16][4];
#pragma unroll
    for (int i = 0; i < 16; i++)
#pragma unroll
        for (int e = 0; e < 4; e++) O[i][e] = 0.f;
    float mrow[2] = {NEG_INF, NEG_INF};
    float lrow[2] = {0.f, 0.f};

    const int ntiles = 2 * qt + 2;
    for (int t = 0; t < ntiles; t++) {
        const int jb = t * FA_KT;
        __syncthreads();

        {
            const int row = tid >> 2;
            const int c0 = (tid & 3) * 32;
            const size_t so = (size_t)(b * SEQ + jb + row) * HIDDEN + h * HEAD_SIZE + c0;
            const uint4* sh = (const uint4*)(gkh + so);
            const uint4* sl = (const uint4*)(gkl + so);
            uint4* dh = (uint4*)(Kh + row * KPS + c0);
            uint4* dl = (uint4*)(Kl + row * KPS + c0);
#pragma unroll
            for (int i = 0; i < 4; i++) { dh[i] = sh[i]; dl[i] = sl[i]; }
        }
        {
            const int d  = tid & 127;
            const int jh = tid >> 7;
            const size_t so = (size_t)(h * HEAD_SIZE + d) * TOTAL + b * SEQ + jb + jh * 32;
            const uint4* sh = (const uint4*)(gvth + so);
            const uint4* sl = (const uint4*)(gvtl + so);
            uint4* dh = (uint4*)(Vh + d * VPS + jh * 32);
            uint4* dl = (uint4*)(Vl + d * VPS + jh * 32);
#pragma unroll
            for (int i = 0; i < 4; i++) { dh[i] = sh[i]; dl[i] = sl[i]; }
        }
        __syncthreads();

        if (jb <= qlo + 15) {
            float sc[8][4];
#pragma unroll
            for (int nb = 0; nb < 8; nb++)
#pragma unroll
                for (int e = 0; e < 4; e++) sc[nb][e] = 0.f;

#pragma unroll
            for (int ks = 0; ks < 8; ks++) {
                const int kb = ks * 16 + cg * 2;
                unsigned qh[4], ql[4];
                {
                    const __nv_bfloat16* p = Qh + (wid * 16 + r) * QPS + kb;
                    qh[0] = *(const unsigned*)p;
                    qh[1] = *(const unsigned*)(p + 8 * QPS);
                    qh[2] = *(const unsigned*)(p + 8);
                    qh[3] = *(const unsigned*)(p + 8 * QPS + 8);
                    const __nv_bfloat16* q2 = Ql + (wid * 16 + r) * QPS + kb;
                    ql[0] = *(const unsigned*)q2;
                    ql[1] = *(const unsigned*)(q2 + 8 * QPS);
                    ql[2] = *(const unsigned*)(q2 + 8);
                    ql[3] = *(const unsigned*)(q2 + 8 * QPS + 8);
                }
                unsigned kf[8][2];
#pragma unroll
                for (int nb = 0; nb < 8; nb++) {
                    const __nv_bfloat16* p = Kh + (nb * 8 + r) * KPS + kb;
                    kf[nb][0] = *(const unsigned*)p;
                    kf[nb][1] = *(const unsigned*)(p + 8);
                }
#pragma unroll
                for (int nb = 0; nb < 8; nb++) mma_bf16(sc[nb], qh, kf[nb]);
#pragma unroll
                for (int nb = 0; nb < 8; nb++) mma_bf16(sc[nb], ql, kf[nb]);
#pragma unroll
                for (int nb = 0; nb < 8; nb++) {
                    const __nv_bfloat16* p = Kl + (nb * 8 + r) * KPS + kb;
                    kf[nb][0] = *(const unsigned*)p;
                    kf[nb][1] = *(const unsigned*)(p + 8);
                }
#pragma unroll
                for (int nb = 0; nb < 8; nb++) mma_bf16(sc[nb], qh, kf[nb]);
            }

            float rmax[2] = {NEG_INF, NEG_INF};
#pragma unroll
            for (int nb = 0; nb < 8; nb++) {
                const int jc = jb + nb * 8 + cg * 2;
                if (jc     > q0) sc[nb][0] = NEG_INF;
                if (jc + 1 > q0) sc[nb][1] = NEG_INF;
                if (jc     > q1) sc[nb][2] = NEG_INF;
                if (jc + 1 > q1) sc[nb][3] = NEG_INF;
                rmax[0] = fmaxf(rmax[0], fmaxf(sc[nb][0], sc[nb][1]));
                rmax[1] = fmaxf(rmax[1], fmaxf(sc[nb][2], sc[nb][3]));
            }
#pragma unroll
            for (int i = 0; i < 2; i++) {
                rmax[i] = fmaxf(rmax[i], __shfl_xor_sync(0xffffffffu, rmax[i], 1));
                rmax[i] = fmaxf(rmax[i], __shfl_xor_sync(0xffffffffu, rmax[i], 2));
            }
            float mnew[2], corr[2];
#pragma unroll
            for (int i = 0; i < 2; i++) {
                mnew[i] = fmaxf(mrow[i], rmax[i]);
                corr[i] = __expf(mrow[i] - mnew[i]);
                lrow[i] *= corr[i];
                mrow[i] = mnew[i];
            }
#pragma unroll
            for (int nb = 0; nb < 16; nb++) {
                O[nb][0] *= corr[0]; O[nb][1] *= corr[0];
                O[nb][2] *= corr[1]; O[nb][3] *= corr[1];
            }
            float psum[2] = {0.f, 0.f};
#pragma unroll
            for (int nb = 0; nb < 8; nb++) {
                float p0 = __expf(sc[nb][0] - mnew[0]);
                float p1 = __expf(sc[nb][1] - mnew[0]);
                float p2 = __expf(sc[nb][2] - mnew[1]);
                float p3 = __expf(sc[nb][3] - mnew[1]);
                sc[nb][0] = p0; sc[nb][1] = p1; sc[nb][2] = p2; sc[nb][3] = p3;
                psum[0] += p0 + p1;
                psum[1] += p2 + p3;
            }
#pragma unroll
            for (int i = 0; i < 2; i++) {
                psum[i] += __shfl_xor_sync(0xffffffffu, psum[i], 1);
                psum[i] += __shfl_xor_sync(0xffffffffu, psum[i], 2);
                lrow[i] += psum[i];
            }

#pragma unroll
            for (int kc = 0; kc < 4; kc++) {
                const float* pa = sc[2 * kc];
                const float* pb = sc[2 * kc + 1];
                float ha0 = __bfloat162float(__float2bfloat16(pa[0]));
                float ha1 = __bfloat162float(__float2bfloat16(pa[1]));
                float ha2 = __bfloat162float(__float2bfloat16(pa[2]));
                float ha3 = __bfloat162float(__float2bfloat16(pa[3]));
                float hb0 = __bfloat162float(__float2bfloat16(pb[0]));
                float hb1 = __bfloat162float(__float2bfloat16(pb[1]));
                float hb2 = __bfloat162float(__float2bfloat16(pb[2]));
                float hb3 = __bfloat162float(__float2bfloat16(pb[3]));
                unsigned ph[4], pl[4];
                ph[0] = pack_bf2(pa[0], pa[1]);
                ph[1] = pack_bf2(pa[2], pa[3]);
                ph[2] = pack_bf2(pb[0], pb[1]);
                ph[3] = pack_bf2(pb[2], pb[3]);
                pl[0] = pack_bf2(pa[0] - ha0, pa[1] - ha1);
                pl[1] = pack_bf2(pa[2] - ha2, pa[3] - ha3);
                pl[2] = pack_bf2(pb[0] - hb0, pb[1] - hb1);
                pl[3] = pack_bf2(pb[2] - hb2, pb[3] - hb3);

                const int kb = kc * 16 + cg * 2;
                unsigned vf[2];
#pragma unroll
                for (int nb = 0; nb < 16; nb++) {
                    const __nv_bfloat16* p = Vh + (nb * 8 + r) * VPS + kb;
                    vf[0] = *(const unsigned*)p;
                    vf[1] = *(const unsigned*)(p + 8);
                    mma_bf16(O[nb], ph, vf);
                }
#pragma unroll
                for (int nb = 0; nb < 16; nb++) {
                    const __nv_bfloat16* p = Vh + (nb * 8 + r) * VPS + kb;
                    vf[0] = *(const unsigned*)p;
                    vf[1] = *(const unsigned*)(p + 8);
                    mma_bf16(O[nb], pl, vf);
                }
#pragma unroll
                for (int nb = 0; nb < 16; nb++) {
                    const __nv_bfloat16* p = Vl + (nb * 8 + r) * VPS + kb;
                    vf[0] = *(const unsigned*)p;
                    vf[1] = *(const unsigned*)(p + 8);
                    mma_bf16(O[nb], ph, vf);
                }
            }
        }
    }

    const float inv0 = 1.0f / lrow[0];
    const float inv1 = 1.0f / lrow[1];
    const size_t base0 = (size_t)(b * SEQ + q0) * HIDDEN + h * HEAD_SIZE;
    const size_t base1 = (size_t)(b * SEQ + q1) * HIDDEN + h * HEAD_SIZE;
#pragma unroll
    for (int nb = 0; nb < 16; nb++) {
        const int d = nb * 8 + cg * 2;
        *(unsigned*)(out_h + base0 + d) = pack_hf2(O[nb][0] * inv0, O[nb][1] * inv0);
        *(unsigned*)(out_h + base1 + d) = pack_hf2(O[nb][2] * inv1, O[nb][3] * inv1);
    }
}

// ---------------------------------------------------------------------------
extern "C" void kernel_launch(void* const* d_in, const int* in_sizes, int n_in,
                              void* d_out, int out_size) {
    const float* hidden  = nullptr;
    const float* w_qkv   = nullptr;
    const float* b_qkv   = nullptr;
    const float* w_dense = nullptr;
    const float* b_dense = nullptr;

    for (int i = 0; i < n_in; i++) {
        switch (in_sizes[i]) {
            case 8388608:  hidden  = (const float*)d_in[i]; break;
            case 12582912: w_qkv   = (const float*)d_in[i]; break;
            case 6144:     b_qkv   = (const float*)d_in[i]; break;
            case 4194304:  w_dense = (const float*)d_in[i]; break;
            case 2048:     b_dense = (const float*)d_in[i]; break;
            default: break;
        }
    }
    if (!hidden)  hidden  = (const float*)d_in[0];
    if (!w_qkv)   w_qkv   = (const float*)d_in[2];
    if (!b_qkv)   b_qkv   = (const float*)d_in[3];
    if (!w_dense) w_dense = (const float*)d_in[4];
    if (!b_dense) b_dense = (const float*)d_in[5];

    float* out = (float*)d_out;

    float* qkv;  cudaGetSymbolAddress((void**)&qkv, g_qkv);
    __half *hid_h, *wqkv_h, *wd_h, *attn_h;
    cudaGetSymbolAddress((void**)&hid_h,  g_hid_h);
    cudaGetSymbolAddress((void**)&wqkv_h, g_wqkv_h);
    cudaGetSymbolAddress((void**)&wd_h,   g_wd_h);
    cudaGetSymbolAddress((void**)&attn_h, g_attn_h);
    __nv_bfloat16 *qh, *ql, *kh, *kl, *vth, *vtl;
    cudaGetSymbolAddress((void**)&qh,  g_qh);
    cudaGetSymbolAddress((void**)&ql,  g_ql);
    cudaGetSymbolAddress((void**)&kh,  g_kh);
    cudaGetSymbolAddress((void**)&kl,  g_kl);
    cudaGetSymbolAddress((void**)&vth, g_vth);
    cudaGetSymbolAddress((void**)&vtl, g_vtl);

    cudaFuncSetAttribute(gemm_f16_nt_bias, cudaFuncAttributeMaxDynamicSharedMemorySize,
                         GEMM_SMEM_BYTES);
    cudaFuncSetAttribute(flash_attn_mma, cudaFuncAttributeMaxDynamicSharedMemorySize,
                         FA_SMEM_BYTES);

    // 0) fp16 conversions
    {
        int n1 = TOTAL * HIDDEN / 4;
        cvt_f16_v4<<<(n1 + 255) / 256, 256>>>((const float4*)hidden, (uint2*)hid_h, n1);
        int n2 = QKV_N * HIDDEN / 4;
        cvt_f16_v4<<<(n2 + 255) / 256, 256>>>((const float4*)w_qkv, (uint2*)wqkv_h, n2);
        int n3 = HIDDEN * HIDDEN / 4;
        cvt_f16_v4<<<(n3 + 255) / 256, 256>>>((const float4*)w_dense, (uint2*)wd_h, n3);
    }
    // 1) QKV GEMM (1-product fp16 HMMA, BK=64)
    {
        dim3 grid(QKV_N / 128, TOTAL / 128);
        gemm_f16_nt_bias<<<grid, 256, GEMM_SMEM_BYTES>>>(hid_h, wqkv_h, b_qkv, qkv,
                                                         QKV_N, HIDDEN);
    }
    // 2) rotary + Q/K split; V split-transpose
    rotary_split_qk<<<TOTAL, 256>>>(qkv, qh, ql, kh, kl);
    {
        dim3 grid(SEQ / 64, HEAD_SIZE / 64, BATCH * NUM_HEADS);
        v_split_T<<<grid, 256>>>(qkv, vth, vtl);
    }
    // 3) flash attention (bf16 3-product) -> fp16
    {
        dim3 grid(SEQ / FA_QT, NUM_HEADS, BATCH);
        flash_attn_mma<<<grid, 256, FA_SMEM_BYTES>>>(qh, ql, kh, kl, vth, vtl, attn_h);
    }
    // 4) dense GEMM (1-product fp16 HMMA, BK=64)
    {
        dim3 grid(HIDDEN / 128, TOTAL / 128);
        gemm_f16_nt_bias<<<grid, 256, GEMM_SMEM_BYTES>>>(attn_h, wd_h, b_dense, out,
                                                         HIDDEN, HIDDEN);
    }
}

// round 15
// speedup vs baseline: 1.0883x; 1.0883x over previous
#include <cuda_runtime.h>
#include <cuda_bf16.h>
#include <cuda_fp16.h>
#include <math.h>
#include <stdint.h>

// Problem constants
#define NUM_HEADS 16
#define HIDDEN 2048
#define HEAD_SIZE 128
#define ROTARY_DIM 32
#define ROTARY_HALF 16
#define BATCH 4
#define SEQ 1024
#define TOTAL (BATCH * SEQ)
#define QKV_N (3 * HIDDEN)
#define QKV_ROW 6144
#define HEAD_STRIDE 384

#define NEG_INF (-1e30f)

// Scratch
__device__ float g_qkv[(size_t)TOTAL * QKV_N];
__device__ __half g_hid_h[(size_t)TOTAL * HIDDEN];
__device__ __half g_wqkv_h[(size_t)QKV_N * HIDDEN];
__device__ __half g_wd_h[(size_t)HIDDEN * HIDDEN];
__device__ __half g_attn_h[(size_t)TOTAL * HIDDEN];
// Precomputed split attention operands (bf16)
__device__ __nv_bfloat16 g_qh[(size_t)TOTAL * HIDDEN];
__device__ __nv_bfloat16 g_ql[(size_t)TOTAL * HIDDEN];
__device__ __nv_bfloat16 g_kh[(size_t)TOTAL * HIDDEN];
__device__ __nv_bfloat16 g_kl[(size_t)TOTAL * HIDDEN];
// V transposed split: [h*128+d][b*1024+j]
__device__ __nv_bfloat16 g_vth[(size_t)NUM_HEADS * HEAD_SIZE * TOTAL];
__device__ __nv_bfloat16 g_vtl[(size_t)NUM_HEADS * HEAD_SIZE * TOTAL];

// ---------------------------------------------------------------------------
__device__ __forceinline__ void mma_bf16(float* d, const unsigned* a, const unsigned* b) {
    asm volatile(
        "mma.sync.aligned.m16n8k16.row.col.f32.bf16.bf16.f32 "
        "{%0,%1,%2,%3}, {%4,%5,%6,%7}, {%8,%9}, {%0,%1,%2,%3};"
        : "+f"(d[0]), "+f"(d[1]), "+f"(d[2]), "+f"(d[3])
        : "r"(a[0]), "r"(a[1]), "r"(a[2]), "r"(a[3]), "r"(b[0]), "r"(b[1]));
}
__device__ __forceinline__ void mma_f16(float* d, const unsigned* a, const unsigned* b) {
    asm volatile(
        "mma.sync.aligned.m16n8k16.row.col.f32.f16.f16.f32 "
        "{%0,%1,%2,%3}, {%4,%5,%6,%7}, {%8,%9}, {%0,%1,%2,%3};"
        : "+f"(d[0]), "+f"(d[1]), "+f"(d[2]), "+f"(d[3])
        : "r"(a[0]), "r"(a[1]), "r"(a[2]), "r"(a[3]), "r"(b[0]), "r"(b[1]));
}

__device__ __forceinline__ void ldsm_x4(unsigned* r, unsigned saddr) {
    asm volatile("ldmatrix.sync.aligned.m8n8.x4.shared.b16 {%0,%1,%2,%3}, [%4];"
        : "=r"(r[0]), "=r"(r[1]), "=r"(r[2]), "=r"(r[3]) : "r"(saddr));
}

__device__ __forceinline__ unsigned pack_bf2(float lo, float hi) {
    __nv_bfloat162 t = __floats2bfloat162_rn(lo, hi);
    return *reinterpret_cast<unsigned*>(&t);
}
__device__ __forceinline__ unsigned pack_hf2(float lo, float hi) {
    __half2 t = __floats2half2_rn(lo, hi);
    return *reinterpret_cast<unsigned*>(&t);
}

__device__ __forceinline__ void cp16h(__half* smem_dst, const __half* gsrc) {
    unsigned saddr = (unsigned)__cvta_generic_to_shared(smem_dst);
    asm volatile("cp.async.cg.shared.global [%0], [%1], 16;" :: "r"(saddr), "l"(gsrc));
}
#define CP_COMMIT() asm volatile("cp.async.commit_group;" ::: "memory")
#define CP_WAIT2()  asm volatile("cp.async.wait_group 2;" ::: "memory")

// ---------------------------------------------------------------------------
// Single-product fp16 NT GEMM on HMMA (exact R13 configuration — measured
// 347.6us QKV): CTA 128x128, 8 warps, BK=32, 4-stage cp.async, ldmatrix,
// 2 CTAs/SM.
// ---------------------------------------------------------------------------
#define PS 40
#define MAT_ELEMS (128 * PS)
#define STAGE_ELEMS (2 * MAT_ELEMS)
#define NSTAGES 4
#define GEMM_SMEM_BYTES (NSTAGES * STAGE_ELEMS * 2)   // 81920 bytes

__global__ __launch_bounds__(256, 2)
void gemm_f16_nt_bias(const __half* __restrict__ A, const __half* __restrict__ B,
                      const float* __restrict__ bias, float* __restrict__ C,
                      int N, int K) {
    extern __shared__ __half smem[];
    const unsigned sbase = (unsigned)__cvta_generic_to_shared(smem);
    const int tid  = threadIdx.x;
    const int lane = tid & 31;
    const int wid  = tid >> 5;
    const int bm = blockIdx.y * 128;
    const int bn = blockIdx.x * 128;
    const int wm = (wid >> 1) * 32;
    const int wn = (wid & 1) * 64;

    float acc[2][8][4];
#pragma unroll
    for (int i = 0; i < 2; i++)
#pragma unroll
        for (int j = 0; j < 8; j++)
#pragma unroll
            for (int k = 0; k < 4; k++) acc[i][j][k] = 0.f;

    const int ldrow = tid >> 1;
    const int ldoff = (tid & 1) * 16;
    const __half* gA = A + (size_t)(bm + ldrow) * K + ldoff;
    const __half* gB = B + (size_t)(bn + ldrow) * K + ldoff;
    const int eo = ldrow * PS + ldoff;

    auto issue_load = [&](int c, int s) {
        const int off = c * 32;
        __half* st = smem + s * STAGE_ELEMS + eo;
        cp16h(st,                 gA + off);
        cp16h(st + 8,             gA + off + 8);
        cp16h(st + MAT_ELEMS,     gB + off);
        cp16h(st + MAT_ELEMS + 8, gB + off + 8);
    };

    const int li = lane & 7;
    const int lm = lane >> 3;
    const int aoff0 = (wm + 0  + (lm & 1) * 8 + li) * PS + (lm >> 1) * 8;
    const int aoff1 = (wm + 16 + (lm & 1) * 8 + li) * PS + (lm >> 1) * 8;
    int boff[4];
#pragma unroll
    for (int p = 0; p < 4; p++)
        boff[p] = (wn + p * 16 + (lm >> 1) * 8 + li) * PS + (lm & 1) * 8;

    auto compute = [&](int s) {
        const unsigned stg = sbase + (s * STAGE_ELEMS) * 2;
        const unsigned sA = stg;
        const unsigned sB = stg + MAT_ELEMS * 2;
#pragma unroll
        for (int ks = 0; ks < 2; ks++) {
            const int kc2 = ks * 16 * 2;
            unsigned a[2][4];
            ldsm_x4(a[0], sA + aoff0 * 2 + kc2);
            ldsm_x4(a[1], sA + aoff1 * 2 + kc2);
            unsigned bh[4][4];
#pragma unroll
            for (int p = 0; p < 4; p++)
                ldsm_x4(bh[p], sB + boff[p] * 2 + kc2);
#pragma unroll
            for (int nf = 0; nf < 8; nf++) {
                const unsigned* bf = &bh[nf >> 1][(nf & 1) * 2];
                mma_f16(acc[0][nf], a[0], bf);
                mma_f16(acc[1][nf], a[1], bf);
            }
        }
    };

    const int nchunks = K / 32;
    issue_load(0, 0); CP_COMMIT();
    issue_load(1, 1); CP_COMMIT();
    issue_load(2, 2); CP_COMMIT();

    int s = 0;
    for (int c = 0; c < nchunks; c++) {
        CP_WAIT2();
        __syncthreads();
        compute(s);
        if (c + 3 < nchunks) issue_load(c + 3, (s + 3) & 3);
        CP_COMMIT();
        s = (s + 1) & 3;
    }

    const int r = lane >> 2;
#pragma unroll
    for (int mf = 0; mf < 2; mf++) {
        const int row0 = bm + wm + mf * 16 + r;
#pragma unroll
        for (int nf = 0; nf < 8; nf++) {
            const int cn = bn + wn + nf * 8 + (lane & 3) * 2;
            float2 o0, o1;
            o0.x = acc[mf][nf][0] + bias[cn];
            o0.y = acc[mf][nf][1] + bias[cn + 1];
            o1.x = acc[mf][nf][2] + bias[cn];
            o1.y = acc[mf][nf][3] + bias[cn + 1];
            *(float2*)(C + (size_t)row0 * N + cn)       = o0;
            *(float2*)(C + (size_t)(row0 + 8) * N + cn) = o1;
        }
    }
}

// ---------------------------------------------------------------------------
__global__ __launch_bounds__(256)
void cvt_f16_v4(const float4* __restrict__ x, uint2* __restrict__ hi, int n4) {
    int i = blockIdx.x * 256 + threadIdx.x;
    if (i >= n4) return;
    float4 v = x[i];
    uint2 ho;
    ho.x = pack_hf2(v.x, v.y);
    ho.y = pack_hf2(v.z, v.w);
    hi[i] = ho;
}

// ---------------------------------------------------------------------------
// Fused rotary + bf16 hi/lo split of Q (scale folded) and K (validated R12).
// ---------------------------------------------------------------------------
__global__ __launch_bounds__(256)
void rotary_split_qk(const float* __restrict__ qkv,
                     __nv_bfloat16* __restrict__ qh, __nv_bfloat16* __restrict__ ql,
                     __nv_bfloat16* __restrict__ kh, __nv_bfloat16* __restrict__ kl) {
    const int t = blockIdx.x;
    const int n0 = threadIdx.x * 8;
    const int h = n0 >> 7;
    const int d0 = n0 & 127;
    const float scale = 0.088388347648318447f;
    const float pos = (float)(t % SEQ);

    const float* qb = qkv + (size_t)t * QKV_ROW + h * HEAD_STRIDE;
    float qv[8], kv[8];
#pragma unroll
    for (int i = 0; i < 8; i++) {
        const int d = d0 + i;
        float xq = qb[d], xk = qb[HEAD_SIZE + d];
        if (d < ROTARY_DIM) {
            const int j = (d < ROTARY_HALF) ? d : d - ROTARY_HALF;
            const float inv_freq = powf(10000.0f, -(2.0f * (float)j) / (float)ROTARY_DIM);
            const float f = pos * inv_freq;
            const float c = cosf(f);
            const float s = sinf(f);
            if (d < ROTARY_HALF) {
                float xq2 = qb[d + ROTARY_HALF], xk2 = qb[HEAD_SIZE + d + ROTARY_HALF];
                xq = xq * c - xq2 * s;
                xk = xk * c - xk2 * s;
            } else {
                float xq1 = qb[d - ROTARY_HALF], xk1 = qb[HEAD_SIZE + d - ROTARY_HALF];
                xq = xq1 * s + xq * c;
                xk = xk1 * s + xk * c;
            }
        }
        qv[i] = xq * scale;
        kv[i] = xk;
    }

    const size_t o = (size_t)t * HIDDEN + n0;
    unsigned rqh[4], rql[4], rkh[4], rkl[4];
#pragma unroll
    for (int i = 0; i < 4; i++) {
        float a = qv[2 * i], b2 = qv[2 * i + 1];
        float ha = __bfloat162float(__float2bfloat16(a));
        float hb = __bfloat162float(__float2bfloat16(b2));
        rqh[i] = pack_bf2(a, b2);
        rql[i] = pack_bf2(a - ha, b2 - hb);
        float ka = kv[2 * i], kb2 = kv[2 * i + 1];
        float hka = __bfloat162float(__float2bfloat16(ka));
        float hkb = __bfloat162float(__float2bfloat16(kb2));
        rkh[i] = pack_bf2(ka, kb2);
        rkl[i] = pack_bf2(ka - hka, kb2 - hkb);
    }
    *(uint4*)(qh + o) = *(uint4*)rqh;
    *(uint4*)(ql + o) = *(uint4*)rql;
    *(uint4*)(kh + o) = *(uint4*)rkh;
    *(uint4*)(kl + o) = *(uint4*)rkl;
}

// ---------------------------------------------------------------------------
// V split + transpose (validated R12).
// ---------------------------------------------------------------------------
__global__ __launch_bounds__(256)
void v_split_T(const float* __restrict__ qkv,
               __nv_bfloat16* __restrict__ vth, __nv_bfloat16* __restrict__ vtl) {
    __shared__ float s[64][65];
    const int tid = threadIdx.x;
    const int j0 = blockIdx.x * 64;
    const int d0 = blockIdx.y * 64;
    const int b  = blockIdx.z >> 4;
    const int h  = blockIdx.z & 15;

    {
        const int jr = tid >> 4;
        const int c4 = (tid & 15) * 4;
#pragma unroll
        for (int it = 0; it < 4; it++) {
            const int j = jr + it * 16;
            const float* src = qkv + (size_t)(b * SEQ + j0 + j) * QKV_ROW
                               + h * HEAD_STRIDE + 2 * HEAD_SIZE + d0 + c4;
            float4 v = *(const float4*)src;
            s[j][c4 + 0] = v.x; s[j][c4 + 1] = v.y;
            s[j][c4 + 2] = v.z; s[j][c4 + 3] = v.w;
        }
    }
    __syncthreads();

    {
        const int d = tid >> 2;
        const int part = tid & 3;
        unsigned rh[8], rl[8];
#pragma unroll
        for (int i = 0; i < 8; i++) {
            float a = s[part * 16 + 2 * i][d];
            float b2 = s[part * 16 + 2 * i + 1][d];
            float ha = __bfloat162float(__float2bfloat16(a));
            float hb = __bfloat162float(__float2bfloat16(b2));
            rh[i] = pack_bf2(a, b2);
            rl[i] = pack_bf2(a - ha, b2 - hb);
        }
        const size_t o = (size_t)(h * HEAD_SIZE + d0 + d) * TOTAL + b * SEQ + j0 + part * 16;
        *(uint4*)(vth + o)     = *(uint4*)rh;
        *(uint4*)(vth + o + 8) = *(uint4*)(rh + 4);
        *(uint4*)(vtl + o)     = *(uint4*)rl;
        *(uint4*)(vtl + o + 8) = *(uint4*)(rl + 4);
    }
}

// ---------------------------------------------------------------------------
// HMMA flash attention (bf16 3-product). P·V now loads each Vh fragment once
// and issues both ph and pl MMAs against it (1/3 fewer V fragment LDS).
// ---------------------------------------------------------------------------
#define QPS 136
#define KPS 136
#define VPS 72
#define FA_QT 128
#define FA_KT 64
#define FA_SMEM_BYTES ((2 * 128 * QPS + 2 * 64 * KPS + 2 * 128 * VPS) * 2)

__global__ __launch_bounds__(256)
void flash_attn_mma(const __nv_bfloat16* __restrict__ gqh, const __nv_bfloat16* __restrict__ gql,
                    const __nv_bfloat16* __restrict__ gkh, const __nv_bfloat16* __restrict__ gkl,
                    const __nv_bfloat16* __restrict__ gvth, const __nv_bfloat16* __restrict__ gvtl,
                    __half* __restrict__ out_h) {
    extern __shared__ __nv_bfloat16 sm[];
    __nv_bfloat16* Qh = sm;
    __nv_bfloat16* Ql = Qh + 128 * QPS;
    __nv_bfloat16* Kh = Ql + 128 * QPS;
    __nv_bfloat16* Kl = Kh + 64 * KPS;
    __nv_bfloat16* Vh = Kl + 64 * KPS;
    __nv_bfloat16* Vl = Vh + 128 * VPS;

    const int qt = blockIdx.x, h = blockIdx.y, b = blockIdx.z;
    const int tid = threadIdx.x, lane = tid & 31, wid = tid >> 5;
    const int r = lane >> 2, cg = lane & 3;
    const int qbase = qt * FA_QT;

    {
        const int row = tid >> 1;
        const int c0 = (tid & 1) * 64;
        const size_t so = (size_t)(b * SEQ + qbase + row) * HIDDEN + h * HEAD_SIZE + c0;
        const uint4* sh = (const uint4*)(gqh + so);
        const uint4* sl = (const uint4*)(gql + so);
        uint4* dh = (uint4*)(Qh + row * QPS + c0);
        uint4* dl = (uint4*)(Ql + row * QPS + c0);
#pragma unroll
        for (int i = 0; i < 8; i++) { dh[i] = sh[i]; dl[i] = sl[i]; }
    }

    const int qlo = qbase + wid * 16;
    const int q0 = qlo + r, q1 = q0 + 8;

    float O[16][4];
#pragma unroll
    for (int i = 0; i < 16; i++)
#pragma unroll
        for (int e = 0; e < 4; e++) O[i][e] = 0.f;
    float mrow[2] = {NEG_INF, NEG_INF};
    float lrow[2] = {0.f, 0.f};

    const int ntiles = 2 * qt + 2;
    for (int t = 0; t < ntiles; t++) {
        const int jb = t * FA_KT;
        __syncthreads();

        {
            const int row = tid >> 2;
            const int c0 = (tid & 3) * 32;
            const size_t so = (size_t)(b * SEQ + jb + row) * HIDDEN + h * HEAD_SIZE + c0;
            const uint4* sh = (const uint4*)(gkh + so);
            const uint4* sl = (const uint4*)(gkl + so);
            uint4* dh = (uint4*)(Kh + row * KPS + c0);
            uint4* dl = (uint4*)(Kl + row * KPS + c0);
#pragma unroll
            for (int i = 0; i < 4; i++) { dh[i] = sh[i]; dl[i] = sl[i]; }
        }
        {
            const int d  = tid & 127;
            const int jh = tid >> 7;
            const size_t so = (size_t)(h * HEAD_SIZE + d) * TOTAL + b * SEQ + jb + jh * 32;
            const uint4* sh = (const uint4*)(gvth + so);
            const uint4* sl = (const uint4*)(gvtl + so);
            uint4* dh = (uint4*)(Vh + d * VPS + jh * 32);
            uint4* dl = (uint4*)(Vl + d * VPS + jh * 32);
#pragma unroll
            for (int i = 0; i < 4; i++) { dh[i] = sh[i]; dl[i] = sl[i]; }
        }
        __syncthreads();

        if (jb <= qlo + 15) {
            float sc[8][4];
#pragma unroll
            for (int nb = 0; nb < 8; nb++)
#pragma unroll
                for (int e = 0; e < 4; e++) sc[nb][e] = 0.f;

#pragma unroll
            for (int ks = 0; ks < 8; ks++) {
                const int kb = ks * 16 + cg * 2;
                unsigned qh[4], ql[4];
                {
                    const __nv_bfloat16* p = Qh + (wid * 16 + r) * QPS + kb;
                    qh[0] = *(const unsigned*)p;
                    qh[1] = *(const unsigned*)(p + 8 * QPS);
                    qh[2] = *(const unsigned*)(p + 8);
                    qh[3] = *(const unsigned*)(p + 8 * QPS + 8);
                    const __nv_bfloat16* q2 = Ql + (wid * 16 + r) * QPS + kb;
                    ql[0] = *(const unsigned*)q2;
                    ql[1] = *(const unsigned*)(q2 + 8 * QPS);
                    ql[2] = *(const unsigned*)(q2 + 8);
                    ql[3] = *(const unsigned*)(q2 + 8 * QPS + 8);
                }
                unsigned kf[8][2];
#pragma unroll
                for (int nb = 0; nb < 8; nb++) {
                    const __nv_bfloat16* p = Kh + (nb * 8 + r) * KPS + kb;
                    kf[nb][0] = *(const unsigned*)p;
                    kf[nb][1] = *(const unsigned*)(p + 8);
                }
#pragma unroll
                for (int nb = 0; nb < 8; nb++) mma_bf16(sc[nb], qh, kf[nb]);
#pragma unroll
                for (int nb = 0; nb < 8; nb++) mma_bf16(sc[nb], ql, kf[nb]);
#pragma unroll
                for (int nb = 0; nb < 8; nb++) {
                    const __nv_bfloat16* p = Kl + (nb * 8 + r) * KPS + kb;
                    kf[nb][0] = *(const unsigned*)p;
                    kf[nb][1] = *(const unsigned*)(p + 8);
                }
#pragma unroll
                for (int nb = 0; nb < 8; nb++) mma_bf16(sc[nb], qh, kf[nb]);
            }

            float rmax[2] = {NEG_INF, NEG_INF};
#pragma unroll
            for (int nb = 0; nb < 8; nb++) {
                const int jc = jb + nb * 8 + cg * 2;
                if (jc     > q0) sc[nb][0] = NEG_INF;
                if (jc + 1 > q0) sc[nb][1] = NEG_INF;
                if (jc     > q1) sc[nb][2] = NEG_INF;
                if (jc + 1 > q1) sc[nb][3] = NEG_INF;
                rmax[0] = fmaxf(rmax[0], fmaxf(sc[nb][0], sc[nb][1]));
                rmax[1] = fmaxf(rmax[1], fmaxf(sc[nb][2], sc[nb][3]));
            }
#pragma unroll
            for (int i = 0; i < 2; i++) {
                rmax[i] = fmaxf(rmax[i], __shfl_xor_sync(0xffffffffu, rmax[i], 1));
                rmax[i] = fmaxf(rmax[i], __shfl_xor_sync(0xffffffffu, rmax[i], 2));
            }
            float mnew[2], corr[2];
#pragma unroll
            for (int i = 0; i < 2; i++) {
                mnew[i] = fmaxf(mrow[i], rmax[i]);
                corr[i] = __expf(mrow[i] - mnew[i]);
                lrow[i] *= corr[i];
                mrow[i] = mnew[i];
            }
#pragma unroll
            for (int nb = 0; nb < 16; nb++) {
                O[nb][0] *= corr[0]; O[nb][1] *= corr[0];
                O[nb][2] *= corr[1]; O[nb][3] *= corr[1];
            }
            float psum[2] = {0.f, 0.f};
#pragma unroll
            for (int nb = 0; nb < 8; nb++) {
                float p0 = __expf(sc[nb][0] - mnew[0]);
                float p1 = __expf(sc[nb][1] - mnew[0]);
                float p2 = __expf(sc[nb][2] - mnew[1]);
                float p3 = __expf(sc[nb][3] - mnew[1]);
                sc[nb][0] = p0; sc[nb][1] = p1; sc[nb][2] = p2; sc[nb][3] = p3;
                psum[0] += p0 + p1;
                psum[1] += p2 + p3;
            }
#pragma unroll
            for (int i = 0; i < 2; i++) {
                psum[i] += __shfl_xor_sync(0xffffffffu, psum[i], 1);
                psum[i] += __shfl_xor_sync(0xffffffffu, psum[i], 2);
                lrow[i] += psum[i];
            }

#pragma unroll
            for (int kc = 0; kc < 4; kc++) {
                const float* pa = sc[2 * kc];
                const float* pb = sc[2 * kc + 1];
                float ha0 = __bfloat162float(__float2bfloat16(pa[0]));
                float ha1 = __bfloat162float(__float2bfloat16(pa[1]));
                float ha2 = __bfloat162float(__float2bfloat16(pa[2]));
                float ha3 = __bfloat162float(__float2bfloat16(pa[3]));
                float hb0 = __bfloat162float(__float2bfloat16(pb[0]));
                float hb1 = __bfloat162float(__float2bfloat16(pb[1]));
                float hb2 = __bfloat162float(__float2bfloat16(pb[2]));
                float hb3 = __bfloat162float(__float2bfloat16(pb[3]));
                unsigned ph[4], pl[4];
                ph[0] = pack_bf2(pa[0], pa[1]);
                ph[1] = pack_bf2(pa[2], pa[3]);
                ph[2] = pack_bf2(pb[0], pb[1]);
                ph[3] = pack_bf2(pb[2], pb[3]);
                pl[0] = pack_bf2(pa[0] - ha0, pa[1] - ha1);
                pl[1] = pack_bf2(pa[2] - ha2, pa[3] - ha3);
                pl[2] = pack_bf2(pb[0] - hb0, pb[1] - hb1);
                pl[3] = pack_bf2(pb[2] - hb2, pb[3] - hb3);

                const int kb = kc * 16 + cg * 2;
                unsigned vf[2];
                // Vh pass: one fragment load feeds both ph and pl MMAs
#pragma unroll
                for (int nb = 0; nb < 16; nb++) {
                    const __nv_bfloat16* p = Vh + (nb * 8 + r) * VPS + kb;
                    vf[0] = *(const unsigned*)p;
                    vf[1] = *(const unsigned*)(p + 8);
                    mma_bf16(O[nb], ph, vf);
                    mma_bf16(O[nb], pl, vf);
                }
                // Vl pass (ph only)
#pragma unroll
                for (int nb = 0; nb < 16; nb++) {
                    const __nv_bfloat16* p = Vl + (nb * 8 + r) * VPS + kb;
                    vf[0] = *(const unsigned*)p;
                    vf[1] = *(const unsigned*)(p + 8);
                    mma_bf16(O[nb], ph, vf);
                }
            }
        }
    }

    const float inv0 = 1.0f / lrow[0];
    const float inv1 = 1.0f / lrow[1];
    const size_t base0 = (size_t)(b * SEQ + q0) * HIDDEN + h * HEAD_SIZE;
    const size_t base1 = (size_t)(b * SEQ + q1) * HIDDEN + h * HEAD_SIZE;
#pragma unroll
    for (int nb = 0; nb < 16; nb++) {
        const int d = nb * 8 + cg * 2;
        *(unsigned*)(out_h + base0 + d) = pack_hf2(O[nb][0] * inv0, O[nb][1] * inv0);
        *(unsigned*)(out_h + base1 + d) = pack_hf2(O[nb][2] * inv1, O[nb][3] * inv1);
    }
}

// ---------------------------------------------------------------------------
extern "C" void kernel_launch(void* const* d_in, const int* in_sizes, int n_in,
                              void* d_out, int out_size) {
    const float* hidden  = nullptr;
    const float* w_qkv   = nullptr;
    const float* b_qkv   = nullptr;
    const float* w_dense = nullptr;
    const float* b_dense = nullptr;

    for (int i = 0; i < n_in; i++) {
        switch (in_sizes[i]) {
            case 8388608:  hidden  = (const float*)d_in[i]; break;
            case 12582912: w_qkv   = (const float*)d_in[i]; break;
            case 6144:     b_qkv   = (const float*)d_in[i]; break;
            case 4194304:  w_dense = (const float*)d_in[i]; break;
            case 2048:     b_dense = (const float*)d_in[i]; break;
            default: break;
        }
    }
    if (!hidden)  hidden  = (const float*)d_in[0];
    if (!w_qkv)   w_qkv   = (const float*)d_in[2];
    if (!b_qkv)   b_qkv   = (const float*)d_in[3];
    if (!w_dense) w_dense = (const float*)d_in[4];
    if (!b_dense) b_dense = (const float*)d_in[5];

    float* out = (float*)d_out;

    float* qkv;  cudaGetSymbolAddress((void**)&qkv, g_qkv);
    __half *hid_h, *wqkv_h, *wd_h, *attn_h;
    cudaGetSymbolAddress((void**)&hid_h,  g_hid_h);
    cudaGetSymbolAddress((void**)&wqkv_h, g_wqkv_h);
    cudaGetSymbolAddress((void**)&wd_h,   g_wd_h);
    cudaGetSymbolAddress((void**)&attn_h, g_attn_h);
    __nv_bfloat16 *qh, *ql, *kh, *kl, *vth, *vtl;
    cudaGetSymbolAddress((void**)&qh,  g_qh);
    cudaGetSymbolAddress((void**)&ql,  g_ql);
    cudaGetSymbolAddress((void**)&kh,  g_kh);
    cudaGetSymbolAddress((void**)&kl,  g_kl);
    cudaGetSymbolAddress((void**)&vth, g_vth);
    cudaGetSymbolAddress((void**)&vtl, g_vtl);

    cudaFuncSetAttribute(gemm_f16_nt_bias, cudaFuncAttributeMaxDynamicSharedMemorySize,
                         GEMM_SMEM_BYTES);
    cudaFuncSetAttribute(flash_attn_mma, cudaFuncAttributeMaxDynamicSharedMemorySize,
                         FA_SMEM_BYTES);

    // 0) fp16 conversions
    {
        int n1 = TOTAL * HIDDEN / 4;
        cvt_f16_v4<<<(n1 + 255) / 256, 256>>>((const float4*)hidden, (uint2*)hid_h, n1);
        int n2 = QKV_N * HIDDEN / 4;
        cvt_f16_v4<<<(n2 + 255) / 256, 256>>>((const float4*)w_qkv, (uint2*)wqkv_h, n2);
        int n3 = HIDDEN * HIDDEN / 4;
        cvt_f16_v4<<<(n3 + 255) / 256, 256>>>((const float4*)w_dense, (uint2*)wd_h, n3);
    }
    // 1) QKV GEMM (1-product fp16 HMMA, BK=32)
    {
        dim3 grid(QKV_N / 128, TOTAL / 128);
        gemm_f16_nt_bias<<<grid, 256, GEMM_SMEM_BYTES>>>(hid_h, wqkv_h, b_qkv, qkv,
                                                         QKV_N, HIDDEN);
    }
    // 2) rotary + Q/K split; V split-transpose
    rotary_split_qk<<<TOTAL, 256>>>(qkv, qh, ql, kh, kl);
    {
        dim3 grid(SEQ / 64, HEAD_SIZE / 64, BATCH * NUM_HEADS);
        v_split_T<<<grid, 256>>>(qkv, vth, vtl);
    }
    // 3) flash attention (bf16 3-product) -> fp16
    {
        dim3 grid(SEQ / FA_QT, NUM_HEADS, BATCH);
        flash_attn_mma<<<grid, 256, FA_SMEM_BYTES>>>(qh, ql, kh, kl, vth, vtl, attn_h);
    }
    // 4) dense GEMM (1-product fp16 HMMA, BK=32)
    {
        dim3 grid(HIDDEN / 128, TOTAL / 128);
        gemm_f16_nt_bias<<<grid, 256, GEMM_SMEM_BYTES>>>(attn_h, wd_h, b_dense, out,
                                                         HIDDEN, HIDDEN);
    }
}

// round 16
// speedup vs baseline: 1.1121x; 1.0218x over previous
#include <cuda_runtime.h>
#include <cuda_bf16.h>
#include <cuda_fp16.h>
#include <math.h>
#include <stdint.h>

// Problem constants
#define NUM_HEADS 16
#define HIDDEN 2048
#define HEAD_SIZE 128
#define ROTARY_DIM 32
#define ROTARY_HALF 16
#define BATCH 4
#define SEQ 1024
#define TOTAL (BATCH * SEQ)
#define QKV_N (3 * HIDDEN)

#define NEG_INF (-1e30f)

// Scratch
__device__ __half g_hid_h[(size_t)TOTAL * HIDDEN];
__device__ __half g_wqkv_h[(size_t)QKV_N * HIDDEN];
__device__ __half g_wd_h[(size_t)HIDDEN * HIDDEN];
__device__ __half g_attn_h[(size_t)TOTAL * HIDDEN];
// Split attention operands (bf16)
__device__ __nv_bfloat16 g_qh[(size_t)TOTAL * HIDDEN];
__device__ __nv_bfloat16 g_ql[(size_t)TOTAL * HIDDEN];
__device__ __nv_bfloat16 g_kh[(size_t)TOTAL * HIDDEN];
__device__ __nv_bfloat16 g_kl[(size_t)TOTAL * HIDDEN];
// V untransposed split (written by fused epilogue)
__device__ __nv_bfloat16 g_vhn[(size_t)TOTAL * HIDDEN];
__device__ __nv_bfloat16 g_vln[(size_t)TOTAL * HIDDEN];
// V transposed split: [h*128+d][b*1024+j]
__device__ __nv_bfloat16 g_vth[(size_t)NUM_HEADS * HEAD_SIZE * TOTAL];
__device__ __nv_bfloat16 g_vtl[(size_t)NUM_HEADS * HEAD_SIZE * TOTAL];

// ---------------------------------------------------------------------------
__device__ __forceinline__ void mma_bf16(float* d, const unsigned* a, const unsigned* b) {
    asm volatile(
        "mma.sync.aligned.m16n8k16.row.col.f32.bf16.bf16.f32 "
        "{%0,%1,%2,%3}, {%4,%5,%6,%7}, {%8,%9}, {%0,%1,%2,%3};"
        : "+f"(d[0]), "+f"(d[1]), "+f"(d[2]), "+f"(d[3])
        : "r"(a[0]), "r"(a[1]), "r"(a[2]), "r"(a[3]), "r"(b[0]), "r"(b[1]));
}
__device__ __forceinline__ void mma_f16(float* d, const unsigned* a, const unsigned* b) {
    asm volatile(
        "mma.sync.aligned.m16n8k16.row.col.f32.f16.f16.f32 "
        "{%0,%1,%2,%3}, {%4,%5,%6,%7}, {%8,%9}, {%0,%1,%2,%3};"
        : "+f"(d[0]), "+f"(d[1]), "+f"(d[2]), "+f"(d[3])
        : "r"(a[0]), "r"(a[1]), "r"(a[2]), "r"(a[3]), "r"(b[0]), "r"(b[1]));
}

__device__ __forceinline__ void ldsm_x4(unsigned* r, unsigned saddr) {
    asm volatile("ldmatrix.sync.aligned.m8n8.x4.shared.b16 {%0,%1,%2,%3}, [%4];"
        : "=r"(r[0]), "=r"(r[1]), "=r"(r[2]), "=r"(r[3]) : "r"(saddr));
}

__device__ __forceinline__ unsigned pack_bf2(float lo, float hi) {
    __nv_bfloat162 t = __floats2bfloat162_rn(lo, hi);
    return *reinterpret_cast<unsigned*>(&t);
}
__device__ __forceinline__ unsigned pack_hf2(float lo, float hi) {
    __half2 t = __floats2half2_rn(lo, hi);
    return *reinterpret_cast<unsigned*>(&t);
}

__device__ __forceinline__ void cp16h(__half* smem_dst, const __half* gsrc) {
    unsigned saddr = (unsigned)__cvta_generic_to_shared(smem_dst);
    asm volatile("cp.async.cg.shared.global [%0], [%1], 16;" :: "r"(saddr), "l"(gsrc));
}
#define CP_COMMIT() asm volatile("cp.async.commit_group;" ::: "memory")
#define CP_WAIT2()  asm volatile("cp.async.wait_group 2;" ::: "memory")

// ---------------------------------------------------------------------------
// Shared GEMM mainloop configuration (validated R13: BK=32, 4-stage, ldmatrix)
// ---------------------------------------------------------------------------
#define PS 40
#define MAT_ELEMS (128 * PS)
#define STAGE_ELEMS (2 * MAT_ELEMS)
#define NSTAGES 4
#define GEMM_SMEM_BYTES (NSTAGES * STAGE_ELEMS * 2)   // 81920 bytes

// Mainloop macro body (identical for both GEMM kernels)
#define GEMM_MAINLOOP(Aptr, Bptr, Kdim)                                        \
    extern __shared__ __half smem[];                                           \
    const unsigned sbase = (unsigned)__cvta_generic_to_shared(smem);           \
    const int tid  = threadIdx.x;                                              \
    const int lane = tid & 31;                                                 \
    const int wid  = tid >> 5;                                                 \
    const int bm = blockIdx.y * 128;                                           \
    const int bn = blockIdx.x * 128;                                           \
    const int wm = (wid >> 1) * 32;                                            \
    const int wn = (wid & 1) * 64;                                             \
    float acc[2][8][4];                                                        \
    _Pragma("unroll")                                                          \
    for (int i = 0; i < 2; i++)                                                \
        _Pragma("unroll")                                                      \
        for (int j = 0; j < 8; j++)                                            \
            _Pragma("unroll")                                                  \
            for (int k = 0; k < 4; k++) acc[i][j][k] = 0.f;                    \
    const int ldrow = tid >> 1;                                                \
    const int ldoff = (tid & 1) * 16;                                          \
    const __half* gA = (Aptr) + (size_t)(bm + ldrow) * (Kdim) + ldoff;         \
    const __half* gB = (Bptr) + (size_t)(bn + ldrow) * (Kdim) + ldoff;         \
    const int eo = ldrow * PS + ldoff;                                         \
    auto issue_load = [&](int c, int s) {                                      \
        const int off = c * 32;                                                \
        __half* st = smem + s * STAGE_ELEMS + eo;                              \
        cp16h(st,                 gA + off);                                   \
        cp16h(st + 8,             gA + off + 8);                               \
        cp16h(st + MAT_ELEMS,     gB + off);                                   \
        cp16h(st + MAT_ELEMS + 8, gB + off + 8);                               \
    };                                                                         \
    const int li = lane & 7;                                                   \
    const int lm = lane >> 3;                                                  \
    const int aoff0 = (wm + 0  + (lm & 1) * 8 + li) * PS + (lm >> 1) * 8;      \
    const int aoff1 = (wm + 16 + (lm & 1) * 8 + li) * PS + (lm >> 1) * 8;      \
    int boff[4];                                                               \
    _Pragma("unroll")                                                          \
    for (int p = 0; p < 4; p++)                                                \
        boff[p] = (wn + p * 16 + (lm >> 1) * 8 + li) * PS + (lm & 1) * 8;      \
    auto compute = [&](int s) {                                                \
        const unsigned stg = sbase + (s * STAGE_ELEMS) * 2;                    \
        const unsigned sA = stg;                                               \
        const unsigned sB = stg + MAT_ELEMS * 2;                               \
        _Pragma("unroll")                                                      \
        for (int ks = 0; ks < 2; ks++) {                                       \
            const int kc2 = ks * 16 * 2;                                       \
            unsigned a[2][4];                                                  \
            ldsm_x4(a[0], sA + aoff0 * 2 + kc2);                               \
            ldsm_x4(a[1], sA + aoff1 * 2 + kc2);                               \
            unsigned bh[4][4];                                                 \
            _Pragma("unroll")                                                  \
            for (int p = 0; p < 4; p++)                                        \
                ldsm_x4(bh[p], sB + boff[p] * 2 + kc2);                        \
            _Pragma("unroll")                                                  \
            for (int nf = 0; nf < 8; nf++) {                                   \
                const unsigned* bf = &bh[nf >> 1][(nf & 1) * 2];               \
                mma_f16(acc[0][nf], a[0], bf);                                 \
                mma_f16(acc[1][nf], a[1], bf);                                 \
            }                                                                  \
        }                                                                      \
    };                                                                         \
    const int nchunks = (Kdim) / 32;                                           \
    issue_load(0, 0); CP_COMMIT();                                             \
    issue_load(1, 1); CP_COMMIT();                                             \
    issue_load(2, 2); CP_COMMIT();                                             \
    int s = 0;                                                                 \
    for (int c = 0; c < nchunks; c++) {                                        \
        CP_WAIT2();                                                            \
        __syncthreads();                                                       \
        compute(s);                                                            \
        if (c + 3 < nchunks) issue_load(c + 3, (s + 3) & 3);                   \
        CP_COMMIT();                                                           \
        s = (s + 1) & 3;                                                       \
    }

// ---------------------------------------------------------------------------
// Dense GEMM: fp32 output + bias (unchanged, validated R13)
// ---------------------------------------------------------------------------
__global__ __launch_bounds__(256, 2)
void gemm_f16_nt_bias(const __half* __restrict__ A, const __half* __restrict__ B,
                      const float* __restrict__ bias, float* __restrict__ C,
                      int N, int K) {
    GEMM_MAINLOOP(A, B, K)

    const int r = lane >> 2;
#pragma unroll
    for (int mf = 0; mf < 2; mf++) {
        const int row0 = bm + wm + mf * 16 + r;
#pragma unroll
        for (int nf = 0; nf < 8; nf++) {
            const int cn = bn + wn + nf * 8 + (lane & 3) * 2;
            float2 o0, o1;
            o0.x = acc[mf][nf][0] + bias[cn];
            o0.y = acc[mf][nf][1] + bias[cn + 1];
            o1.x = acc[mf][nf][2] + bias[cn];
            o1.y = acc[mf][nf][3] + bias[cn + 1];
            *(float2*)(C + (size_t)row0 * N + cn)       = o0;
            *(float2*)(C + (size_t)(row0 + 8) * N + cn) = o1;
        }
    }
}

// ---------------------------------------------------------------------------
// QKV GEMM with fused bias + rotary + q-scale + bf16 hi/lo split epilogue.
// Each 128-col tile is exactly one head's q, k, or v block (6144 = 16*384).
// Rotary pair (d, d+16) = fragment cols (nf, nf+2) of the SAME thread (wn==0).
// ---------------------------------------------------------------------------
__global__ __launch_bounds__(256, 2)
void gemm_qkv_fused(const __half* __restrict__ A, const __half* __restrict__ B,
                    const float* __restrict__ bias,
                    __nv_bfloat16* __restrict__ qh, __nv_bfloat16* __restrict__ ql,
                    __nv_bfloat16* __restrict__ kh, __nv_bfloat16* __restrict__ kl,
                    __nv_bfloat16* __restrict__ vhn, __nv_bfloat16* __restrict__ vln) {
    GEMM_MAINLOOP(A, B, HIDDEN)

    const int r   = lane >> 2;
    const int cg2 = (lane & 3) * 2;
    const int head = bn / 384;
    const int off3 = bn % 384;            // 0=q, 128=k, 256=v
    const float scale = 0.088388347648318447f;

    // 1) bias (b_qkv column layout matches global n = bn + wn + nf*8 + cg2)
#pragma unroll
    for (int mf = 0; mf < 2; mf++)
#pragma unroll
        for (int nf = 0; nf < 8; nf++) {
            const float b0 = bias[bn + wn + nf * 8 + cg2];
            const float b1 = bias[bn + wn + nf * 8 + cg2 + 1];
            acc[mf][nf][0] += b0; acc[mf][nf][1] += b1;
            acc[mf][nf][2] += b0; acc[mf][nf][3] += b1;
        }

    // 2) rotary for q/k blocks (cols d<32 live in wn==0, nf<4; pair = nf,nf+2)
    if (off3 != 256 && wn == 0) {
#pragma unroll
        for (int mf = 0; mf < 2; mf++) {
            const int row0 = bm + wm + mf * 16 + r;
#pragma unroll
            for (int nf = 0; nf < 2; nf++) {
#pragma unroll
                for (int e = 0; e < 2; e++) {
                    const int j = nf * 8 + cg2 + e;   // 0..15
                    const float inv_freq = powf(10000.0f, -(2.0f * (float)j) / (float)ROTARY_DIM);
                    {
                        const float pos = (float)(row0 & (SEQ - 1));
                        const float f = pos * inv_freq;
                        const float c = cosf(f), sn = sinf(f);
                        float x1 = acc[mf][nf][e], x2 = acc[mf][nf + 2][e];
                        acc[mf][nf][e]     = x1 * c - x2 * sn;
                        acc[mf][nf + 2][e] = x1 * sn + x2 * c;
                    }
                    {
                        const float pos = (float)((row0 + 8) & (SEQ - 1));
                        const float f = pos * inv_freq;
                        const float c = cosf(f), sn = sinf(f);
                        float x1 = acc[mf][nf][e + 2], x2 = acc[mf][nf + 2][e + 2];
                        acc[mf][nf][e + 2]     = x1 * c - x2 * sn;
                        acc[mf][nf + 2][e + 2] = x1 * sn + x2 * c;
                    }
                }
            }
        }
    }

    // 3) q scale (after rotary, matching validated order)
    if (off3 == 0) {
#pragma unroll
        for (int mf = 0; mf < 2; mf++)
#pragma unroll
            for (int nf = 0; nf < 8; nf++)
#pragma unroll
                for (int e = 0; e < 4; e++) acc[mf][nf][e] *= scale;
    }

    // 4) split to bf16 hi/lo, store at [row][head*128 + d]
    __nv_bfloat16* dsth = (off3 == 0) ? qh : (off3 == 128) ? kh : vhn;
    __nv_bfloat16* dstl = (off3 == 0) ? ql : (off3 == 128) ? kl : vln;
#pragma unroll
    for (int mf = 0; mf < 2; mf++) {
        const int row0 = bm + wm + mf * 16 + r;
#pragma unroll
        for (int nf = 0; nf < 8; nf++) {
            const int dl = wn + nf * 8 + cg2;
            const size_t o0 = (size_t)row0 * HIDDEN + head * HEAD_SIZE + dl;
            const size_t o1 = o0 + 8 * HIDDEN;
            float a0 = acc[mf][nf][0], a1 = acc[mf][nf][1];
            float a2 = acc[mf][nf][2], a3 = acc[mf][nf][3];
            float h0 = __bfloat162float(__float2bfloat16(a0));
            float h1 = __bfloat162float(__float2bfloat16(a1));
            float h2 = __bfloat162float(__float2bfloat16(a2));
            float h3 = __bfloat162float(__float2bfloat16(a3));
            *(unsigned*)(dsth + o0) = pack_bf2(a0, a1);
            *(unsigned*)(dstl + o0) = pack_bf2(a0 - h0, a1 - h1);
            *(unsigned*)(dsth + o1) = pack_bf2(a2, a3);
            *(unsigned*)(dstl + o1) = pack_bf2(a2 - h2, a3 - h3);
        }
    }
}

// ---------------------------------------------------------------------------
__global__ __launch_bounds__(256)
void cvt_f16_v4(const float4* __restrict__ x, uint2* __restrict__ hi, int n4) {
    int i = blockIdx.x * 256 + threadIdx.x;
    if (i >= n4) return;
    float4 v = x[i];
    uint2 ho;
    ho.x = pack_hf2(v.x, v.y);
    ho.y = pack_hf2(v.z, v.w);
    hi[i] = ho;
}

// ---------------------------------------------------------------------------
// bf16 V transpose: [t][h*128+d] -> [h*128+d][t], both hi and lo streams.
// Tile 64j x 64d via SMEM. grid = (16, 2, 64).
// ---------------------------------------------------------------------------
__global__ __launch_bounds__(256)
void v_transpose_bf16(const __nv_bfloat16* __restrict__ vhn,
                      const __nv_bfloat16* __restrict__ vln,
                      __nv_bfloat16* __restrict__ vth,
                      __nv_bfloat16* __restrict__ vtl) {
    __shared__ unsigned short s[64][72];
    const int tid = threadIdx.x;
    const int j0 = blockIdx.x * 64;
    const int d0 = blockIdx.y * 64;
    const int b  = blockIdx.z >> 4;
    const int h  = blockIdx.z & 15;

    const __nv_bfloat16* srcs[2] = {vhn, vln};
    __nv_bfloat16* dsts[2] = {vth, vtl};

#pragma unroll
    for (int m = 0; m < 2; m++) {
        {
            const int jr = tid >> 3;          // 0..31
            const int c8 = (tid & 7) * 8;
#pragma unroll
            for (int it = 0; it < 2; it++) {
                const int j = jr + it * 32;
                uint4 v = *(const uint4*)(srcs[m] + (size_t)(b * SEQ + j0 + j) * HIDDEN
                                          + h * HEAD_SIZE + d0 + c8);
                *(uint4*)&s[j][c8] = v;
            }
        }
        __syncthreads();
        {
            const int dr = tid >> 3;
            const int j8 = (tid & 7) * 8;
#pragma unroll
            for (int it = 0; it < 2; it++) {
                const int d = dr + it * 32;
                unsigned short tmp[8];
#pragma unroll
                for (int k = 0; k < 8; k++) tmp[k] = s[j8 + k][d];
                *(uint4*)(dsts[m] + (size_t)(h * HEAD_SIZE + d0 + d) * TOTAL
                          + b * SEQ + j0 + j8) = *(uint4*)tmp;
            }
        }
        __syncthreads();
    }
}

// ---------------------------------------------------------------------------
// HMMA flash attention (bf16 3-product, validated; merged Vh pass).
// ---------------------------------------------------------------------------
#define QPS 136
#define KPS 136
#define VPS 72
#define FA_QT 128
#define FA_KT 64
#define FA_SMEM_BYTES ((2 * 128 * QPS + 2 * 64 * KPS + 2 * 128 * VPS) * 2)

__global__ __launch_bounds__(256)
void flash_attn_mma(const __nv_bfloat16* __restrict__ gqh, const __nv_bfloat16* __restrict__ gql,
                    const __nv_bfloat16* __restrict__ gkh, const __nv_bfloat16* __restrict__ gkl,
                    const __nv_bfloat16* __restrict__ gvth, const __nv_bfloat16* __restrict__ gvtl,
                    __half* __restrict__ out_h) {
    extern __shared__ __nv_bfloat16 sm[];
    __nv_bfloat16* Qh = sm;
    __nv_bfloat16* Ql = Qh + 128 * QPS;
    __nv_bfloat16* Kh = Ql + 128 * QPS;
    __nv_bfloat16* Kl = Kh + 64 * KPS;
    __nv_bfloat16* Vh = Kl + 64 * KPS;
    __nv_bfloat16* Vl = Vh + 128 * VPS;

    const int qt = blockIdx.x, h = blockIdx.y, b = blockIdx.z;
    const int tid = threadIdx.x, lane = tid & 31, wid = tid >> 5;
    const int r = lane >> 2, cg = lane & 3;
    const int qbase = qt * FA_QT;

    {
        const int row = tid >> 1;
        const int c0 = (tid & 1) * 64;
        const size_t so = (size_t)(b * SEQ + qbase + row) * HIDDEN + h * HEAD_SIZE + c0;
        const uint4* sh = (const uint4*)(gqh + so);
        const uint4* sl = (const uint4*)(gql + so);
        uint4* dh = (uint4*)(Qh + row * QPS + c0);
        uint4* dl = (uint4*)(Ql + row * QPS + c0);
#pragma unroll
        for (int i = 0; i < 8; i++) { dh[i] = sh[i]; dl[i] = sl[i]; }
    }

    const int qlo = qbase + wid * 16;
    const int q0 = qlo + r, q1 = q0 + 8;

    float O[16][4];
#pragma unroll
    for (int i = 0; i < 16; i++)
#pragma unroll
        for (int e = 0; e < 4; e++) O[i][e] = 0.f;
    float mrow[2] = {NEG_INF, NEG_INF};
    float lrow[2] = {0.f, 0.f};

    const int ntiles = 2 * qt + 2;
    for (int t = 0; t < ntiles; t++) {
        const int jb = t * FA_KT;
        __syncthreads();

        {
            const int row = tid >> 2;
            const int c0 = (tid & 3) * 32;
            const size_t so = (size_t)(b * SEQ + jb + row) * HIDDEN + h * HEAD_SIZE + c0;
            const uint4* sh = (const uint4*)(gkh + so);
            const uint4* sl = (const uint4*)(gkl + so);
            uint4* dh = (uint4*)(Kh + row * KPS + c0);
            uint4* dl = (uint4*)(Kl + row * KPS + c0);
#pragma unroll
            for (int i = 0; i < 4; i++) { dh[i] = sh[i]; dl[i] = sl[i]; }
        }
        {
            const int d  = tid & 127;
            const int jh = tid >> 7;
            const size_t so = (size_t)(h * HEAD_SIZE + d) * TOTAL + b * SEQ + jb + jh * 32;
            const uint4* sh = (const uint4*)(gvth + so);
            const uint4* sl = (const uint4*)(gvtl + so);
            uint4* dh = (uint4*)(Vh + d * VPS + jh * 32);
            uint4* dl = (uint4*)(Vl + d * VPS + jh * 32);
#pragma unroll
            for (int i = 0; i < 4; i++) { dh[i] = sh[i]; dl[i] = sl[i]; }
        }
        __syncthreads();

        if (jb <= qlo + 15) {
            float sc[8][4];
#pragma unroll
            for (int nb = 0; nb < 8; nb++)
#pragma unroll
                for (int e = 0; e < 4; e++) sc[nb][e] = 0.f;

#pragma unroll
            for (int ks = 0; ks < 8; ks++) {
                const int kb = ks * 16 + cg * 2;
                unsigned qhf[4], qlf[4];
                {
                    const __nv_bfloat16* p = Qh + (wid * 16 + r) * QPS + kb;
                    qhf[0] = *(const unsigned*)p;
                    qhf[1] = *(const unsigned*)(p + 8 * QPS);
                    qhf[2] = *(const unsigned*)(p + 8);
                    qhf[3] = *(const unsigned*)(p + 8 * QPS + 8);
                    const __nv_bfloat16* q2 = Ql + (wid * 16 + r) * QPS + kb;
                    qlf[0] = *(const unsigned*)q2;
                    qlf[1] = *(const unsigned*)(q2 + 8 * QPS);
                    qlf[2] = *(const unsigned*)(q2 + 8);
                    qlf[3] = *(const unsigned*)(q2 + 8 * QPS + 8);
                }
                unsigned kf[8][2];
#pragma unroll
                for (int nb = 0; nb < 8; nb++) {
                    const __nv_bfloat16* p = Kh + (nb * 8 + r) * KPS + kb;
                    kf[nb][0] = *(const unsigned*)p;
                    kf[nb][1] = *(const unsigned*)(p + 8);
                }
#pragma unroll
                for (int nb = 0; nb < 8; nb++) mma_bf16(sc[nb], qhf, kf[nb]);
#pragma unroll
                for (int nb = 0; nb < 8; nb++) mma_bf16(sc[nb], qlf, kf[nb]);
#pragma unroll
                for (int nb = 0; nb < 8; nb++) {
                    const __nv_bfloat16* p = Kl + (nb * 8 + r) * KPS + kb;
                    kf[nb][0] = *(const unsigned*)p;
                    kf[nb][1] = *(const unsigned*)(p + 8);
                }
#pragma unroll
                for (int nb = 0; nb < 8; nb++) mma_bf16(sc[nb], qhf, kf[nb]);
            }

            float rmax[2] = {NEG_INF, NEG_INF};
#pragma unroll
            for (int nb = 0; nb < 8; nb++) {
                const int jc = jb + nb * 8 + cg * 2;
                if (jc     > q0) sc[nb][0] = NEG_INF;
                if (jc + 1 > q0) sc[nb][1] = NEG_INF;
                if (jc     > q1) sc[nb][2] = NEG_INF;
                if (jc + 1 > q1) sc[nb][3] = NEG_INF;
                rmax[0] = fmaxf(rmax[0], fmaxf(sc[nb][0], sc[nb][1]));
                rmax[1] = fmaxf(rmax[1], fmaxf(sc[nb][2], sc[nb][3]));
            }
#pragma unroll
            for (int i = 0; i < 2; i++) {
                rmax[i] = fmaxf(rmax[i], __shfl_xor_sync(0xffffffffu, rmax[i], 1));
                rmax[i] = fmaxf(rmax[i], __shfl_xor_sync(0xffffffffu, rmax[i], 2));
            }
            float mnew[2], corr[2];
#pragma unroll
            for (int i = 0; i < 2; i++) {
                mnew[i] = fmaxf(mrow[i], rmax[i]);
                corr[i] = __expf(mrow[i] - mnew[i]);
                lrow[i] *= corr[i];
                mrow[i] = mnew[i];
            }
#pragma unroll
            for (int nb = 0; nb < 16; nb++) {
                O[nb][0] *= corr[0]; O[nb][1] *= corr[0];
                O[nb][2] *= corr[1]; O[nb][3] *= corr[1];
            }
            float psum[2] = {0.f, 0.f};
#pragma unroll
            for (int nb = 0; nb < 8; nb++) {
                float p0 = __expf(sc[nb][0] - mnew[0]);
                float p1 = __expf(sc[nb][1] - mnew[0]);
                float p2 = __expf(sc[nb][2] - mnew[1]);
                float p3 = __expf(sc[nb][3] - mnew[1]);
                sc[nb][0] = p0; sc[nb][1] = p1; sc[nb][2] = p2; sc[nb][3] = p3;
                psum[0] += p0 + p1;
                psum[1] += p2 + p3;
            }
#pragma unroll
            for (int i = 0; i < 2; i++) {
                psum[i] += __shfl_xor_sync(0xffffffffu, psum[i], 1);
                psum[i] += __shfl_xor_sync(0xffffffffu, psum[i], 2);
                lrow[i] += psum[i];
            }

#pragma unroll
            for (int kc = 0; kc < 4; kc++) {
                const float* pa = sc[2 * kc];
                const float* pb = sc[2 * kc + 1];
                float ha0 = __bfloat162float(__float2bfloat16(pa[0]));
                float ha1 = __bfloat162float(__float2bfloat16(pa[1]));
                float ha2 = __bfloat162float(__float2bfloat16(pa[2]));
                float ha3 = __bfloat162float(__float2bfloat16(pa[3]));
                float hb0 = __bfloat162float(__float2bfloat16(pb[0]));
                float hb1 = __bfloat162float(__float2bfloat16(pb[1]));
                float hb2 = __bfloat162float(__float2bfloat16(pb[2]));
                float hb3 = __bfloat162float(__float2bfloat16(pb[3]));
                unsigned ph[4], pl[4];
                ph[0] = pack_bf2(pa[0], pa[1]);
                ph[1] = pack_bf2(pa[2], pa[3]);
                ph[2] = pack_bf2(pb[0], pb[1]);
                ph[3] = pack_bf2(pb[2], pb[3]);
                pl[0] = pack_bf2(pa[0] - ha0, pa[1] - ha1);
                pl[1] = pack_bf2(pa[2] - ha2, pa[3] - ha3);
                pl[2] = pack_bf2(pb[0] - hb0, pb[1] - hb1);
                pl[3] = pack_bf2(pb[2] - hb2, pb[3] - hb3);

                const int kb = kc * 16 + cg * 2;
                unsigned vf[2];
#pragma unroll
                for (int nb = 0; nb < 16; nb++) {
                    const __nv_bfloat16* p = Vh + (nb * 8 + r) * VPS + kb;
                    vf[0] = *(const unsigned*)p;
                    vf[1] = *(const unsigned*)(p + 8);
                    mma_bf16(O[nb], ph, vf);
                    mma_bf16(O[nb], pl, vf);
                }
#pragma unroll
                for (int nb = 0; nb < 16; nb++) {
                    const __nv_bfloat16* p = Vl + (nb * 8 + r) * VPS + kb;
                    vf[0] = *(const unsigned*)p;
                    vf[1] = *(const unsigned*)(p + 8);
                    mma_bf16(O[nb], ph, vf);
                }
            }
        }
    }

    const float inv0 = 1.0f / lrow[0];
    const float inv1 = 1.0f / lrow[1];
    const size_t base0 = (size_t)(b * SEQ + q0) * HIDDEN + h * HEAD_SIZE;
    const size_t base1 = (size_t)(b * SEQ + q1) * HIDDEN + h * HEAD_SIZE;
#pragma unroll
    for (int nb = 0; nb < 16; nb++) {
        const int d = nb * 8 + cg * 2;
        *(unsigned*)(out_h + base0 + d) = pack_hf2(O[nb][0] * inv0, O[nb][1] * inv0);
        *(unsigned*)(out_h + base1 + d) = pack_hf2(O[nb][2] * inv1, O[nb][3] * inv1);
    }
}

// ---------------------------------------------------------------------------
extern "C" void kernel_launch(void* const* d_in, const int* in_sizes, int n_in,
                              void* d_out, int out_size) {
    const float* hidden  = nullptr;
    const float* w_qkv   = nullptr;
    const float* b_qkv   = nullptr;
    const float* w_dense = nullptr;
    const float* b_dense = nullptr;

    for (int i = 0; i < n_in; i++) {
        switch (in_sizes[i]) {
            case 8388608:  hidden  = (const float*)d_in[i]; break;
            case 12582912: w_qkv   = (const float*)d_in[i]; break;
            case 6144:     b_qkv   = (const float*)d_in[i]; break;
            case 4194304:  w_dense = (const float*)d_in[i]; break;
            case 2048:     b_dense = (const float*)d_in[i]; break;
            default: break;
        }
    }
    if (!hidden)  hidden  = (const float*)d_in[0];
    if (!w_qkv)   w_qkv   = (const float*)d_in[2];
    if (!b_qkv)   b_qkv   = (const float*)d_in[3];
    if (!w_dense) w_dense = (const float*)d_in[4];
    if (!b_dense) b_dense = (const float*)d_in[5];

    float* out = (float*)d_out;

    __half *hid_h, *wqkv_h, *wd_h, *attn_h;
    cudaGetSymbolAddress((void**)&hid_h,  g_hid_h);
    cudaGetSymbolAddress((void**)&wqkv_h, g_wqkv_h);
    cudaGetSymbolAddress((void**)&wd_h,   g_wd_h);
    cudaGetSymbolAddress((void**)&attn_h, g_attn_h);
    __nv_bfloat16 *qh, *ql, *kh, *kl, *vhn, *vln, *vth, *vtl;
    cudaGetSymbolAddress((void**)&qh,  g_qh);
    cudaGetSymbolAddress((void**)&ql,  g_ql);
    cudaGetSymbolAddress((void**)&kh,  g_kh);
    cudaGetSymbolAddress((void**)&kl,  g_kl);
    cudaGetSymbolAddress((void**)&vhn, g_vhn);
    cudaGetSymbolAddress((void**)&vln, g_vln);
    cudaGetSymbolAddress((void**)&vth, g_vth);
    cudaGetSymbolAddress((void**)&vtl, g_vtl);

    cudaFuncSetAttribute(gemm_f16_nt_bias, cudaFuncAttributeMaxDynamicSharedMemorySize,
                         GEMM_SMEM_BYTES);
    cudaFuncSetAttribute(gemm_qkv_fused, cudaFuncAttributeMaxDynamicSharedMemorySize,
                         GEMM_SMEM_BYTES);
    cudaFuncSetAttribute(flash_attn_mma, cudaFuncAttributeMaxDynamicSharedMemorySize,
                         FA_SMEM_BYTES);

    // 0) fp16 conversions
    {
        int n1 = TOTAL * HIDDEN / 4;
        cvt_f16_v4<<<(n1 + 255) / 256, 256>>>((const float4*)hidden, (uint2*)hid_h, n1);
        int n2 = QKV_N * HIDDEN / 4;
        cvt_f16_v4<<<(n2 + 255) / 256, 256>>>((const float4*)w_qkv, (uint2*)wqkv_h, n2);
        int n3 = HIDDEN * HIDDEN / 4;
        cvt_f16_v4<<<(n3 + 255) / 256, 256>>>((const float4*)w_dense, (uint2*)wd_h, n3);
    }
    // 1) QKV GEMM with fused rotary + split epilogue
    {
        dim3 grid(QKV_N / 128, TOTAL / 128);
        gemm_qkv_fused<<<grid, 256, GEMM_SMEM_BYTES>>>(hid_h, wqkv_h, b_qkv,
                                                       qh, ql, kh, kl, vhn, vln);
    }
    // 2) V transpose (bf16 -> bf16)
    {
        dim3 grid(SEQ / 64, HEAD_SIZE / 64, BATCH * NUM_HEADS);
        v_transpose_bf16<<<grid, 256>>>(vhn, vln, vth, vtl);
    }
    // 3) flash attention (bf16 3-product) -> fp16
    {
        dim3 grid(SEQ / FA_QT, NUM_HEADS, BATCH);
        flash_attn_mma<<<grid, 256, FA_SMEM_BYTES>>>(qh, ql, kh, kl, vth, vtl, attn_h);
    }
    // 4) dense GEMM (1-product fp16 HMMA)
    {
        dim3 grid(HIDDEN / 128, TOTAL / 128);
        gemm_f16_nt_bias<<<grid, 256, GEMM_SMEM_BYTES>>>(attn_h, wd_h, b_dense, out,
                                                         HIDDEN, HIDDEN);
    }
}

// round 17
// speedup vs baseline: 1.2862x; 1.1565x over previous
#include <cuda_runtime.h>
#include <cuda_bf16.h>
#include <cuda_fp16.h>
#include <math.h>
#include <stdint.h>

// Problem constants
#define NUM_HEADS 16
#define HIDDEN 2048
#define HEAD_SIZE 128
#define ROTARY_DIM 32
#define ROTARY_HALF 16
#define BATCH 4
#define SEQ 1024
#define TOTAL (BATCH * SEQ)
#define QKV_N (3 * HIDDEN)

#define NEG_INF (-1e30f)

// Scratch
__device__ __half g_hid_h[(size_t)TOTAL * HIDDEN];
__device__ __half g_wqkv_h[(size_t)QKV_N * HIDDEN];
__device__ __half g_wd_h[(size_t)HIDDEN * HIDDEN];
__device__ __half g_attn_h[(size_t)TOTAL * HIDDEN];
// Attention operands (fp16): Q split hi/lo, K single, V single
__device__ __half g_qh[(size_t)TOTAL * HIDDEN];
__device__ __half g_ql[(size_t)TOTAL * HIDDEN];
__device__ __half g_kh[(size_t)TOTAL * HIDDEN];
__device__ __half g_vhn[(size_t)TOTAL * HIDDEN];
// V transposed: [h*128+d][b*1024+j]
__device__ __half g_vth[(size_t)NUM_HEADS * HEAD_SIZE * TOTAL];

// ---------------------------------------------------------------------------
__device__ __forceinline__ void mma_f16(float* d, const unsigned* a, const unsigned* b) {
    asm volatile(
        "mma.sync.aligned.m16n8k16.row.col.f32.f16.f16.f32 "
        "{%0,%1,%2,%3}, {%4,%5,%6,%7}, {%8,%9}, {%0,%1,%2,%3};"
        : "+f"(d[0]), "+f"(d[1]), "+f"(d[2]), "+f"(d[3])
        : "r"(a[0]), "r"(a[1]), "r"(a[2]), "r"(a[3]), "r"(b[0]), "r"(b[1]));
}

__device__ __forceinline__ void ldsm_x4(unsigned* r, unsigned saddr) {
    asm volatile("ldmatrix.sync.aligned.m8n8.x4.shared.b16 {%0,%1,%2,%3}, [%4];"
        : "=r"(r[0]), "=r"(r[1]), "=r"(r[2]), "=r"(r[3]) : "r"(saddr));
}

__device__ __forceinline__ unsigned pack_hf2(float lo, float hi) {
    __half2 t = __floats2half2_rn(lo, hi);
    return *reinterpret_cast<unsigned*>(&t);
}

__device__ __forceinline__ void cp16h(__half* smem_dst, const __half* gsrc) {
    unsigned saddr = (unsigned)__cvta_generic_to_shared(smem_dst);
    asm volatile("cp.async.cg.shared.global [%0], [%1], 16;" :: "r"(saddr), "l"(gsrc));
}
#define CP_COMMIT() asm volatile("cp.async.commit_group;" ::: "memory")
#define CP_WAIT2()  asm volatile("cp.async.wait_group 2;" ::: "memory")

// ---------------------------------------------------------------------------
// Shared GEMM mainloop (validated R13: BK=32, 4-stage, ldmatrix, 2 CTAs/SM)
// ---------------------------------------------------------------------------
#define PS 40
#define MAT_ELEMS (128 * PS)
#define STAGE_ELEMS (2 * MAT_ELEMS)
#define NSTAGES 4
#define GEMM_SMEM_BYTES (NSTAGES * STAGE_ELEMS * 2)

#define GEMM_MAINLOOP(Aptr, Bptr, Kdim)                                        \
    extern __shared__ __half smem[];                                           \
    const unsigned sbase = (unsigned)__cvta_generic_to_shared(smem);           \
    const int tid  = threadIdx.x;                                              \
    const int lane = tid & 31;                                                 \
    const int wid  = tid >> 5;                                                 \
    const int bm = blockIdx.y * 128;                                           \
    const int bn = blockIdx.x * 128;                                           \
    const int wm = (wid >> 1) * 32;                                            \
    const int wn = (wid & 1) * 64;                                             \
    float acc[2][8][4];                                                        \
    _Pragma("unroll")                                                          \
    for (int i = 0; i < 2; i++)                                                \
        _Pragma("unroll")                                                      \
        for (int j = 0; j < 8; j++)                                            \
            _Pragma("unroll")                                                  \
            for (int k = 0; k < 4; k++) acc[i][j][k] = 0.f;                    \
    const int ldrow = tid >> 1;                                                \
    const int ldoff = (tid & 1) * 16;                                          \
    const __half* gA = (Aptr) + (size_t)(bm + ldrow) * (Kdim) + ldoff;         \
    const __half* gB = (Bptr) + (size_t)(bn + ldrow) * (Kdim) + ldoff;         \
    const int eo = ldrow * PS + ldoff;                                         \
    auto issue_load = [&](int c, int s) {                                      \
        const int off = c * 32;                                                \
        __half* st = smem + s * STAGE_ELEMS + eo;                              \
        cp16h(st,                 gA + off);                                   \
        cp16h(st + 8,             gA + off + 8);                               \
        cp16h(st + MAT_ELEMS,     gB + off);                                   \
        cp16h(st + MAT_ELEMS + 8, gB + off + 8);                               \
    };                                                                         \
    const int li = lane & 7;                                                   \
    const int lm = lane >> 3;                                                  \
    const int aoff0 = (wm + 0  + (lm & 1) * 8 + li) * PS + (lm >> 1) * 8;      \
    const int aoff1 = (wm + 16 + (lm & 1) * 8 + li) * PS + (lm >> 1) * 8;      \
    int boff[4];                                                               \
    _Pragma("unroll")                                                          \
    for (int p = 0; p < 4; p++)                                                \
        boff[p] = (wn + p * 16 + (lm >> 1) * 8 + li) * PS + (lm & 1) * 8;      \
    auto compute = [&](int s) {                                                \
        const unsigned stg = sbase + (s * STAGE_ELEMS) * 2;                    \
        const unsigned sA = stg;                                               \
        const unsigned sB = stg + MAT_ELEMS * 2;                               \
        _Pragma("unroll")                                                      \
        for (int ks = 0; ks < 2; ks++) {                                       \
            const int kc2 = ks * 16 * 2;                                       \
            unsigned a[2][4];                                                  \
            ldsm_x4(a[0], sA + aoff0 * 2 + kc2);                               \
            ldsm_x4(a[1], sA + aoff1 * 2 + kc2);                               \
            unsigned bh[4][4];                                                 \
            _Pragma("unroll")                                                  \
            for (int p = 0; p < 4; p++)                                        \
                ldsm_x4(bh[p], sB + boff[p] * 2 + kc2);                        \
            _Pragma("unroll")                                                  \
            for (int nf = 0; nf < 8; nf++) {                                   \
                const unsigned* bf = &bh[nf >> 1][(nf & 1) * 2];               \
                mma_f16(acc[0][nf], a[0], bf);                                 \
                mma_f16(acc[1][nf], a[1], bf);                                 \
            }                                                                  \
        }                                                                      \
    };                                                                         \
    const int nchunks = (Kdim) / 32;                                           \
    issue_load(0, 0); CP_COMMIT();                                             \
    issue_load(1, 1); CP_COMMIT();                                             \
    issue_load(2, 2); CP_COMMIT();                                             \
    int s = 0;                                                                 \
    for (int c = 0; c < nchunks; c++) {                                        \
        CP_WAIT2();                                                            \
        __syncthreads();                                                       \
        compute(s);                                                            \
        if (c + 3 < nchunks) issue_load(c + 3, (s + 3) & 3);                   \
        CP_COMMIT();                                                           \
        s = (s + 1) & 3;                                                       \
    }

// ---------------------------------------------------------------------------
// Dense GEMM: fp32 output + bias (validated R13)
// ---------------------------------------------------------------------------
__global__ __launch_bounds__(256, 2)
void gemm_f16_nt_bias(const __half* __restrict__ A, const __half* __restrict__ B,
                      const float* __restrict__ bias, float* __restrict__ C,
                      int N, int K) {
    GEMM_MAINLOOP(A, B, K)

    const int r = lane >> 2;
#pragma unroll
    for (int mf = 0; mf < 2; mf++) {
        const int row0 = bm + wm + mf * 16 + r;
#pragma unroll
        for (int nf = 0; nf < 8; nf++) {
            const int cn = bn + wn + nf * 8 + (lane & 3) * 2;
            float2 o0, o1;
            o0.x = acc[mf][nf][0] + bias[cn];
            o0.y = acc[mf][nf][1] + bias[cn + 1];
            o1.x = acc[mf][nf][2] + bias[cn];
            o1.y = acc[mf][nf][3] + bias[cn + 1];
            *(float2*)(C + (size_t)row0 * N + cn)       = o0;
            *(float2*)(C + (size_t)(row0 + 8) * N + cn) = o1;
        }
    }
}

// ---------------------------------------------------------------------------
// QKV GEMM with fused bias + rotary + q-scale + fp16 emit epilogue.
// Q -> hi/lo fp16 split; K -> single fp16; V -> single fp16 (untransposed).
// ---------------------------------------------------------------------------
__global__ __launch_bounds__(256, 2)
void gemm_qkv_fused(const __half* __restrict__ A, const __half* __restrict__ B,
                    const float* __restrict__ bias,
                    __half* __restrict__ qh, __half* __restrict__ ql,
                    __half* __restrict__ kh, __half* __restrict__ vhn) {
    GEMM_MAINLOOP(A, B, HIDDEN)

    const int r   = lane >> 2;
    const int cg2 = (lane & 3) * 2;
    const int head = bn / 384;
    const int off3 = bn % 384;            // 0=q, 128=k, 256=v
    const float scale = 0.088388347648318447f;

    // 1) bias
#pragma unroll
    for (int mf = 0; mf < 2; mf++)
#pragma unroll
        for (int nf = 0; nf < 8; nf++) {
            const float b0 = bias[bn + wn + nf * 8 + cg2];
            const float b1 = bias[bn + wn + nf * 8 + cg2 + 1];
            acc[mf][nf][0] += b0; acc[mf][nf][1] += b1;
            acc[mf][nf][2] += b0; acc[mf][nf][3] += b1;
        }

    // 2) rotary for q/k blocks (validated R16 mapping)
    if (off3 != 256 && wn == 0) {
#pragma unroll
        for (int mf = 0; mf < 2; mf++) {
            const int row0 = bm + wm + mf * 16 + r;
#pragma unroll
            for (int nf = 0; nf < 2; nf++) {
#pragma unroll
                for (int e = 0; e < 2; e++) {
                    const int j = nf * 8 + cg2 + e;
                    const float inv_freq = powf(10000.0f, -(2.0f * (float)j) / (float)ROTARY_DIM);
                    {
                        const float pos = (float)(row0 & (SEQ - 1));
                        const float f = pos * inv_freq;
                        const float c = cosf(f), sn = sinf(f);
                        float x1 = acc[mf][nf][e], x2 = acc[mf][nf + 2][e];
                        acc[mf][nf][e]     = x1 * c - x2 * sn;
                        acc[mf][nf + 2][e] = x1 * sn + x2 * c;
                    }
                    {
                        const float pos = (float)((row0 + 8) & (SEQ - 1));
                        const float f = pos * inv_freq;
                        const float c = cosf(f), sn = sinf(f);
                        float x1 = acc[mf][nf][e + 2], x2 = acc[mf][nf + 2][e + 2];
                        acc[mf][nf][e + 2]     = x1 * c - x2 * sn;
                        acc[mf][nf + 2][e + 2] = x1 * sn + x2 * c;
                    }
                }
            }
        }
    }

    // 3) q scale
    if (off3 == 0) {
#pragma unroll
        for (int mf = 0; mf < 2; mf++)
#pragma unroll
            for (int nf = 0; nf < 8; nf++)
#pragma unroll
                for (int e = 0; e < 4; e++) acc[mf][nf][e] *= scale;
    }

    // 4) emit
#pragma unroll
    for (int mf = 0; mf < 2; mf++) {
        const int row0 = bm + wm + mf * 16 + r;
#pragma unroll
        for (int nf = 0; nf < 8; nf++) {
            const int dl = wn + nf * 8 + cg2;
            const size_t o0 = (size_t)row0 * HIDDEN + head * HEAD_SIZE + dl;
            const size_t o1 = o0 + 8 * HIDDEN;
            float a0 = acc[mf][nf][0], a1 = acc[mf][nf][1];
            float a2 = acc[mf][nf][2], a3 = acc[mf][nf][3];
            if (off3 == 0) {
                float h0 = __half2float(__float2half(a0));
                float h1 = __half2float(__float2half(a1));
                float h2 = __half2float(__float2half(a2));
                float h3 = __half2float(__float2half(a3));
                *(unsigned*)(qh + o0) = pack_hf2(a0, a1);
                *(unsigned*)(ql + o0) = pack_hf2(a0 - h0, a1 - h1);
                *(unsigned*)(qh + o1) = pack_hf2(a2, a3);
                *(unsigned*)(ql + o1) = pack_hf2(a2 - h2, a3 - h3);
            } else if (off3 == 128) {
                *(unsigned*)(kh + o0) = pack_hf2(a0, a1);
                *(unsigned*)(kh + o1) = pack_hf2(a2, a3);
            } else {
                *(unsigned*)(vhn + o0) = pack_hf2(a0, a1);
                *(unsigned*)(vhn + o1) = pack_hf2(a2, a3);
            }
        }
    }
}

// ---------------------------------------------------------------------------
__global__ __launch_bounds__(256)
void cvt_f16_v4(const float4* __restrict__ x, uint2* __restrict__ hi, int n4) {
    int i = blockIdx.x * 256 + threadIdx.x;
    if (i >= n4) return;
    float4 v = x[i];
    uint2 ho;
    ho.x = pack_hf2(v.x, v.y);
    ho.y = pack_hf2(v.z, v.w);
    hi[i] = ho;
}

// ---------------------------------------------------------------------------
// fp16 V transpose: [t][h*128+d] -> [h*128+d][t].
// ---------------------------------------------------------------------------
__global__ __launch_bounds__(256)
void v_transpose_f16(const __half* __restrict__ vhn, __half* __restrict__ vth) {
    __shared__ unsigned short s[64][72];
    const int tid = threadIdx.x;
    const int j0 = blockIdx.x * 64;
    const int d0 = blockIdx.y * 64;
    const int b  = blockIdx.z >> 4;
    const int h  = blockIdx.z & 15;

    {
        const int jr = tid >> 3;
        const int c8 = (tid & 7) * 8;
#pragma unroll
        for (int it = 0; it < 2; it++) {
            const int j = jr + it * 32;
            uint4 v = *(const uint4*)(vhn + (size_t)(b * SEQ + j0 + j) * HIDDEN
                                      + h * HEAD_SIZE + d0 + c8);
            *(uint4*)&s[j][c8] = v;
        }
    }
    __syncthreads();
    {
        const int dr = tid >> 3;
        const int j8 = (tid & 7) * 8;
#pragma unroll
        for (int it = 0; it < 2; it++) {
            const int d = dr + it * 32;
            unsigned short tmp[8];
#pragma unroll
            for (int k = 0; k < 8; k++) tmp[k] = s[j8 + k][d];
            *(uint4*)(vth + (size_t)(h * HEAD_SIZE + d0 + d) * TOTAL
                      + b * SEQ + j0 + j8) = *(uint4*)tmp;
        }
    }
}

// ---------------------------------------------------------------------------
// HMMA flash attention, fp16 2-product both phases:
//   S = (Qh + Ql) * K;  O = (Ph + Pl) * V.
// SMEM: Qh,Ql[128][136], K[64][136], V[128][72] fp16 = 103 KB.
// ---------------------------------------------------------------------------
#define QPS 136
#define KPS 136
#define VPS 72
#define FA_QT 128
#define FA_KT 64
#define FA_SMEM_BYTES ((2 * 128 * QPS + 64 * KPS + 128 * VPS) * 2)

__global__ __launch_bounds__(256)
void flash_attn_mma(const __half* __restrict__ gqh, const __half* __restrict__ gql,
                    const __half* __restrict__ gkh, const __half* __restrict__ gvth,
                    __half* __restrict__ out_h) {
    extern __shared__ __half sm[];
    __half* Qh = sm;
    __half* Ql = Qh + 128 * QPS;
    __half* Ks = Ql + 128 * QPS;
    __half* Vs = Ks + 64 * KPS;

    const int qt = blockIdx.x, h = blockIdx.y, b = blockIdx.z;
    const int tid = threadIdx.x, lane = tid & 31, wid = tid >> 5;
    const int r = lane >> 2, cg = lane & 3;
    const int qbase = qt * FA_QT;

    {
        const int row = tid >> 1;
        const int c0 = (tid & 1) * 64;
        const size_t so = (size_t)(b * SEQ + qbase + row) * HIDDEN + h * HEAD_SIZE + c0;
        const uint4* sh = (const uint4*)(gqh + so);
        const uint4* sl = (const uint4*)(gql + so);
        uint4* dh = (uint4*)(Qh + row * QPS + c0);
        uint4* dl = (uint4*)(Ql + row * QPS + c0);
#pragma unroll
        for (int i = 0; i < 8; i++) { dh[i] = sh[i]; dl[i] = sl[i]; }
    }

    const int qlo = qbase + wid * 16;
    const int q0 = qlo + r, q1 = q0 + 8;

    float O[16][4];
#pragma unroll
    for (int i = 0; i < 16; i++)
#pragma unroll
        for (int e = 0; e < 4; e++) O[i][e] = 0.f;
    float mrow[2] = {NEG_INF, NEG_INF};
    float lrow[2] = {0.f, 0.f};

    const int ntiles = 2 * qt + 2;
    for (int t = 0; t < ntiles; t++) {
        const int jb = t * FA_KT;
        __syncthreads();

        // K tile copy (single stream)
        {
            const int row = tid >> 2;
            const int c0 = (tid & 3) * 32;
            const size_t so = (size_t)(b * SEQ + jb + row) * HIDDEN + h * HEAD_SIZE + c0;
            const uint4* sh = (const uint4*)(gkh + so);
            uint4* dh = (uint4*)(Ks + row * KPS + c0);
#pragma unroll
            for (int i = 0; i < 4; i++) dh[i] = sh[i];
        }
        // V tile copy (single stream)
        {
            const int d  = tid & 127;
            const int jh = tid >> 7;
            const size_t so = (size_t)(h * HEAD_SIZE + d) * TOTAL + b * SEQ + jb + jh * 32;
            const uint4* sh = (const uint4*)(gvth + so);
            uint4* dh = (uint4*)(Vs + d * VPS + jh * 32);
#pragma unroll
            for (int i = 0; i < 4; i++) dh[i] = sh[i];
        }
        __syncthreads();

        if (jb <= qlo + 15) {
            float sc[8][4];
#pragma unroll
            for (int nb = 0; nb < 8; nb++)
#pragma unroll
                for (int e = 0; e < 4; e++) sc[nb][e] = 0.f;

#pragma unroll
            for (int ks = 0; ks < 8; ks++) {
                const int kb = ks * 16 + cg * 2;
                unsigned qhf[4], qlf[4];
                {
                    const __half* p = Qh + (wid * 16 + r) * QPS + kb;
                    qhf[0] = *(const unsigned*)p;
                    qhf[1] = *(const unsigned*)(p + 8 * QPS);
                    qhf[2] = *(const unsigned*)(p + 8);
                    qhf[3] = *(const unsigned*)(p + 8 * QPS + 8);
                    const __half* q2 = Ql + (wid * 16 + r) * QPS + kb;
                    qlf[0] = *(const unsigned*)q2;
                    qlf[1] = *(const unsigned*)(q2 + 8 * QPS);
                    qlf[2] = *(const unsigned*)(q2 + 8);
                    qlf[3] = *(const unsigned*)(q2 + 8 * QPS + 8);
                }
                unsigned kf[8][2];
#pragma unroll
                for (int nb = 0; nb < 8; nb++) {
                    const __half* p = Ks + (nb * 8 + r) * KPS + kb;
                    kf[nb][0] = *(const unsigned*)p;
                    kf[nb][1] = *(const unsigned*)(p + 8);
                }
#pragma unroll
                for (int nb = 0; nb < 8; nb++) mma_f16(sc[nb], qhf, kf[nb]);
#pragma unroll
                for (int nb = 0; nb < 8; nb++) mma_f16(sc[nb], qlf, kf[nb]);
            }

            float rmax[2] = {NEG_INF, NEG_INF};
#pragma unroll
            for (int nb = 0; nb < 8; nb++) {
                const int jc = jb + nb * 8 + cg * 2;
                if (jc     > q0) sc[nb][0] = NEG_INF;
                if (jc + 1 > q0) sc[nb][1] = NEG_INF;
                if (jc     > q1) sc[nb][2] = NEG_INF;
                if (jc + 1 > q1) sc[nb][3] = NEG_INF;
                rmax[0] = fmaxf(rmax[0], fmaxf(sc[nb][0], sc[nb][1]));
                rmax[1] = fmaxf(rmax[1], fmaxf(sc[nb][2], sc[nb][3]));
            }
#pragma unroll
            for (int i = 0; i < 2; i++) {
                rmax[i] = fmaxf(rmax[i], __shfl_xor_sync(0xffffffffu, rmax[i], 1));
                rmax[i] = fmaxf(rmax[i], __shfl_xor_sync(0xffffffffu, rmax[i], 2));
            }
            float mnew[2], corr[2];
#pragma unroll
            for (int i = 0; i < 2; i++) {
                mnew[i] = fmaxf(mrow[i], rmax[i]);
                corr[i] = __expf(mrow[i] - mnew[i]);
                lrow[i] *= corr[i];
                mrow[i] = mnew[i];
            }
#pragma unroll
            for (int nb = 0; nb < 16; nb++) {
                O[nb][0] *= corr[0]; O[nb][1] *= corr[0];
                O[nb][2] *= corr[1]; O[nb][3] *= corr[1];
            }
            float psum[2] = {0.f, 0.f};
#pragma unroll
            for (int nb = 0; nb < 8; nb++) {
                float p0 = __expf(sc[nb][0] - mnew[0]);
                float p1 = __expf(sc[nb][1] - mnew[0]);
                float p2 = __expf(sc[nb][2] - mnew[1]);
                float p3 = __expf(sc[nb][3] - mnew[1]);
                sc[nb][0] = p0; sc[nb][1] = p1; sc[nb][2] = p2; sc[nb][3] = p3;
                psum[0] += p0 + p1;
                psum[1] += p2 + p3;
            }
#pragma unroll
            for (int i = 0; i < 2; i++) {
                psum[i] += __shfl_xor_sync(0xffffffffu, psum[i], 1);
                psum[i] += __shfl_xor_sync(0xffffffffu, psum[i], 2);
                lrow[i] += psum[i];
            }

#pragma unroll
            for (int kc = 0; kc < 4; kc++) {
                const float* pa = sc[2 * kc];
                const float* pb = sc[2 * kc + 1];
                float ha0 = __half2float(__float2half(pa[0]));
                float ha1 = __half2float(__float2half(pa[1]));
                float ha2 = __half2float(__float2half(pa[2]));
                float ha3 = __half2float(__float2half(pa[3]));
                float hb0 = __half2float(__float2half(pb[0]));
                float hb1 = __half2float(__float2half(pb[1]));
                float hb2 = __half2float(__float2half(pb[2]));
                float hb3 = __half2float(__float2half(pb[3]));
                unsigned ph[4], pl[4];
                ph[0] = pack_hf2(pa[0], pa[1]);
                ph[1] = pack_hf2(pa[2], pa[3]);
                ph[2] = pack_hf2(pb[0], pb[1]);
                ph[3] = pack_hf2(pb[2], pb[3]);
                pl[0] = pack_hf2(pa[0] - ha0, pa[1] - ha1);
                pl[1] = pack_hf2(pa[2] - ha2, pa[3] - ha3);
                pl[2] = pack_hf2(pb[0] - hb0, pb[1] - hb1);
                pl[3] = pack_hf2(pb[2] - hb2, pb[3] - hb3);

                const int kb = kc * 16 + cg * 2;
                unsigned vf[2];
#pragma unroll
                for (int nb = 0; nb < 16; nb++) {
                    const __half* p = Vs + (nb * 8 + r) * VPS + kb;
                    vf[0] = *(const unsigned*)p;
                    vf[1] = *(const unsigned*)(p + 8);
                    mma_f16(O[nb], ph, vf);
                    mma_f16(O[nb], pl, vf);
                }
            }
        }
    }

    const float inv0 = 1.0f / lrow[0];
    const float inv1 = 1.0f / lrow[1];
    const size_t base0 = (size_t)(b * SEQ + q0) * HIDDEN + h * HEAD_SIZE;
    const size_t base1 = (size_t)(b * SEQ + q1) * HIDDEN + h * HEAD_SIZE;
#pragma unroll
    for (int nb = 0; nb < 16; nb++) {
        const int d = nb * 8 + cg * 2;
        *(unsigned*)(out_h + base0 + d) = pack_hf2(O[nb][0] * inv0, O[nb][1] * inv0);
        *(unsigned*)(out_h + base1 + d) = pack_hf2(O[nb][2] * inv1, O[nb][3] * inv1);
    }
}

// ---------------------------------------------------------------------------
extern "C" void kernel_launch(void* const* d_in, const int* in_sizes, int n_in,
                              void* d_out, int out_size) {
    const float* hidden  = nullptr;
    const float* w_qkv   = nullptr;
    const float* b_qkv   = nullptr;
    const float* w_dense = nullptr;
    const float* b_dense = nullptr;

    for (int i = 0; i < n_in; i++) {
        switch (in_sizes[i]) {
            case 8388608:  hidden  = (const float*)d_in[i]; break;
            case 12582912: w_qkv   = (const float*)d_in[i]; break;
            case 6144:     b_qkv   = (const float*)d_in[i]; break;
            case 4194304:  w_dense = (const float*)d_in[i]; break;
            case 2048:     b_dense = (const float*)d_in[i]; break;
            default: break;
        }
    }
    if (!hidden)  hidden  = (const float*)d_in[0];
    if (!w_qkv)   w_qkv   = (const float*)d_in[2];
    if (!b_qkv)   b_qkv   = (const float*)d_in[3];
    if (!w_dense) w_dense = (const float*)d_in[4];
    if (!b_dense) b_dense = (const float*)d_in[5];

    float* out = (float*)d_out;

    __half *hid_h, *wqkv_h, *wd_h, *attn_h;
    cudaGetSymbolAddress((void**)&hid_h,  g_hid_h);
    cudaGetSymbolAddress((void**)&wqkv_h, g_wqkv_h);
    cudaGetSymbolAddress((void**)&wd_h,   g_wd_h);
    cudaGetSymbolAddress((void**)&attn_h, g_attn_h);
    __half *qh, *ql, *kh, *vhn, *vth;
    cudaGetSymbolAddress((void**)&qh,  g_qh);
    cudaGetSymbolAddress((void**)&ql,  g_ql);
    cudaGetSymbolAddress((void**)&kh,  g_kh);
    cudaGetSymbolAddress((void**)&vhn, g_vhn);
    cudaGetSymbolAddress((void**)&vth, g_vth);

    cudaFuncSetAttribute(gemm_f16_nt_bias, cudaFuncAttributeMaxDynamicSharedMemorySize,
                         GEMM_SMEM_BYTES);
    cudaFuncSetAttribute(gemm_qkv_fused, cudaFuncAttributeMaxDynamicSharedMemorySize,
                         GEMM_SMEM_BYTES);
    cudaFuncSetAttribute(flash_attn_mma, cudaFuncAttributeMaxDynamicSharedMemorySize,
                         FA_SMEM_BYTES);

    // 0) fp16 conversions
    {
        int n1 = TOTAL * HIDDEN / 4;
        cvt_f16_v4<<<(n1 + 255) / 256, 256>>>((const float4*)hidden, (uint2*)hid_h, n1);
        int n2 = QKV_N * HIDDEN / 4;
        cvt_f16_v4<<<(n2 + 255) / 256, 256>>>((const float4*)w_qkv, (uint2*)wqkv_h, n2);
        int n3 = HIDDEN * HIDDEN / 4;
        cvt_f16_v4<<<(n3 + 255) / 256, 256>>>((const float4*)w_dense, (uint2*)wd_h, n3);
    }
    // 1) QKV GEMM + fused rotary/scale/split
    {
        dim3 grid(QKV_N / 128, TOTAL / 128);
        gemm_qkv_fused<<<grid, 256, GEMM_SMEM_BYTES>>>(hid_h, wqkv_h, b_qkv,
                                                       qh, ql, kh, vhn);
    }
    // 2) V transpose (fp16)
    {
        dim3 grid(SEQ / 64, HEAD_SIZE / 64, BATCH * NUM_HEADS);
        v_transpose_f16<<<grid, 256>>>(vhn, vth);
    }
    // 3) flash attention (fp16 2-product) -> fp16
    {
        dim3 grid(SEQ / FA_QT, NUM_HEADS, BATCH);
        flash_attn_mma<<<grid, 256, FA_SMEM_BYTES>>>(qh, ql, kh, vth, attn_h);
    }
    // 4) dense GEMM
    {
        dim3 grid(HIDDEN / 128, TOTAL / 128);
        gemm_f16_nt_bias<<<grid, 256, GEMM_SMEM_BYTES>>>(attn_h, wd_h, b_dense, out,
                                                         HIDDEN, HIDDEN);
    }
}